// round 12
// baseline (speedup 1.0000x reference)
#include <cuda_runtime.h>
#include <cuda_bf16.h>
#include <cstdint>
#include <math.h>

#define Bn 2
#define Sn 2048
#define Dn 2048
#define HQn 32
#define HKVn 8
#define HDn 64
#define ROWS (Bn * Sn)      // 4096
#define NG   (Bn * HQn)     // 64 attention "heads"
#define NTB64 (Sn / 64)     // 32
#define NTB128 (Sn / 128)   // 16
#define QKVW 3072           // fused q|k|v width
#define QSCALE 0.18033688011112042f   // 0.125 * log2(e)

// ---------------- scratch ----------------
__device__ float g_xn[ROWS * Dn];
__device__ float g_qkv[(size_t)ROWS * QKVW];
__device__ float g_wf[Dn * QKVW];
__device__ float g_bf[QKVW];
__device__ float g_wo[Dn * Dn];
__device__ float g_attn[ROWS * (HQn * HDn)];
__device__ float g_vt[(size_t)Bn * 512 * Sn];      // V transposed: [b][h*64+d][T]
__device__ float g_m[NG * Sn];
__device__ float g_zi[NG * Sn];

// ---------------- helpers ----------------
__device__ __forceinline__ float f2tf(float x) {
    uint32_t r;
    asm("cvt.rna.tf32.f32 %0, %1;" : "=r"(r) : "f"(x));
    return __uint_as_float(r);
}
__device__ __forceinline__ float4 cvt4(float4 v) {
    v.x = f2tf(v.x); v.y = f2tf(v.y); v.z = f2tf(v.z); v.w = f2tf(v.w);
    return v;
}
__device__ __forceinline__ float fex2(float x) {
    float r;
    asm("ex2.approx.ftz.f32 %0, %1;" : "=f"(r) : "f"(x));
    return r;
}
__device__ __forceinline__ void mma8(float* c, const uint32_t* a, uint32_t b0, uint32_t b1) {
    asm volatile(
        "mma.sync.aligned.m16n8k8.row.col.f32.tf32.tf32.f32 "
        "{%0,%1,%2,%3}, {%4,%5,%6,%7}, {%8,%9}, {%0,%1,%2,%3};"
        : "+f"(c[0]), "+f"(c[1]), "+f"(c[2]), "+f"(c[3])
        : "r"(a[0]), "r"(a[1]), "r"(a[2]), "r"(a[3]), "r"(b0), "r"(b1));
}
__device__ __forceinline__ void cpa16(void* dst_smem, const void* src) {
    uint32_t d = (uint32_t)__cvta_generic_to_shared(dst_smem);
    asm volatile("cp.async.cg.shared.global [%0], [%1], 16;" :: "r"(d), "l"(src));
}
#define CP_COMMIT() asm volatile("cp.async.commit_group;")
#define CP_WAIT(n)  asm volatile("cp.async.wait_group %0;" :: "n"(n))
#define F2U(x) __float_as_uint(x)
#define NEGBIG (-1e30f)

// ---------------- fused pre: LN + weight/bias prep ----------------
__global__ __launch_bounds__(256) void fused_pre(
    const float* __restrict__ x, const float* __restrict__ gamma,
    const float* __restrict__ beta,
    const float* __restrict__ Wq, const float* __restrict__ Wk,
    const float* __restrict__ Wv, const float* __restrict__ Wo,
    const float* __restrict__ bq, const float* __restrict__ bk,
    const float* __restrict__ bv,
    float* __restrict__ xn, float* __restrict__ Wf,
    float* __restrict__ Wr, float* __restrict__ bf)
{
    const int blk = blockIdx.x;
    const int tid = threadIdx.x;

    if (blk < ROWS) {
        const int row = blk;
        const float* xr = x + (size_t)row * Dn;
        float* outr = xn + (size_t)row * Dn;
        __shared__ float red[256];

        float s = 0.f;
        for (int c = tid; c < Dn; c += 256) s += xr[c];
        red[tid] = s; __syncthreads();
        for (int off = 128; off > 0; off >>= 1) {
            if (tid < off) red[tid] += red[tid + off];
            __syncthreads();
        }
        const float mu = red[0] * (1.0f / Dn);
        __syncthreads();

        float v = 0.f;
        for (int c = tid; c < Dn; c += 256) { float d = xr[c] - mu; v += d * d; }
        red[tid] = v; __syncthreads();
        for (int off = 128; off > 0; off >>= 1) {
            if (tid < off) red[tid] += red[tid + off];
            __syncthreads();
        }
        const float rstd = rsqrtf(red[0] * (1.0f / Dn) + 1e-5f);
        __syncthreads();

        for (int c = tid; c < Dn; c += 256)
            outr[c] = f2tf((xr[c] - mu) * rstd * gamma[c] + beta[c]);
    } else if (blk < ROWS + 6144) {
        const int idx = ((blk - ROWS) * 256 + tid) * 4;
        const int row = idx / QKVW, col = idx % QKVW;
        const float* src;
        if (col < 2048)      src = &Wq[(size_t)row * 2048 + col];
        else if (col < 2560) src = &Wk[(size_t)row * 512 + col - 2048];
        else                 src = &Wv[(size_t)row * 512 + col - 2560];
        *(float4*)&Wf[idx] = cvt4(*(const float4*)src);
    } else if (blk < ROWS + 6144 + 4096) {
        const int idx = ((blk - ROWS - 6144) * 256 + tid) * 4;
        *(float4*)&Wr[idx] = cvt4(*(const float4*)&Wo[idx]);
    } else {
        const int col = (blk - ROWS - 6144 - 4096) * 256 + tid;
        if (col < QKVW)
            bf[col] = col < 2048 ? bq[col] : (col < 2560 ? bk[col - 2048] : bv[col - 2560]);
    }
}

// ---------------- V transpose: qkv v-part [t][hd] -> vT [hd][t] ----------------
__global__ __launch_bounds__(256) void vtrans(
    const float* __restrict__ QKV, float* __restrict__ vT)
{
    __shared__ float tile[32][33];
    const int b  = blockIdx.z;
    const int hd0 = blockIdx.y * 32;
    const int t0  = blockIdx.x * 32;
    const int tx = threadIdx.x & 31, ty = threadIdx.x >> 5;   // 32 x 8

    #pragma unroll
    for (int i = 0; i < 32; i += 8)
        tile[ty + i][tx] = QKV[(size_t)(b * Sn + t0 + ty + i) * QKVW + 2560 + hd0 + tx];
    __syncthreads();
    #pragma unroll
    for (int i = 0; i < 32; i += 8)
        vT[(size_t)(b * 512 + hd0 + ty + i) * Sn + t0 + tx] = tile[tx][ty + i];
}

// ---------------- cp.async 3-stage tf32 GEMM ----------------
#define STAGES 3
#define GEMM_SMEM (STAGES * (128 * 20 + 16 * 136) * 4)

__global__ __launch_bounds__(256, 2) void gemm_cp(
    const float* __restrict__ A, const float* __restrict__ B,
    const float* __restrict__ bias, float* __restrict__ C,
    int M, int N, int K, float scale0, float scale1, int ncut, int round_out)
{
    extern __shared__ float sm[];
    float (*As)[128][20] = (float(*)[128][20])sm;
    float (*Bs)[16][136] = (float(*)[16][136])(sm + STAGES * 128 * 20);

    const int tid = threadIdx.x;
    const int lane = tid & 31, wid = tid >> 5;
    const int warp_m = wid & 3, warp_n = wid >> 2;
    const int m0 = blockIdx.y * 128, n0 = blockIdx.x * 128;

    const int ar = tid >> 2, ac = (tid & 3) * 4;
    const int br = tid >> 5, bc = (tid & 31) * 4;
    const int lr = lane >> 2, lc = lane & 3;

    const int KT = K / 16;

    float acc[2][8][4];
    #pragma unroll
    for (int i = 0; i < 2; i++)
        #pragma unroll
        for (int j = 0; j < 8; j++)
            #pragma unroll
            for (int q = 0; q < 4; q++) acc[i][j][q] = 0.f;

    #pragma unroll
    for (int s = 0; s < STAGES - 1; s++) {
        const int k0 = s * 16;
        const float* ap = &A[(size_t)(m0 + ar) * K + k0 + ac];
        cpa16(&As[s][ar][ac], ap);
        cpa16(&As[s][ar + 64][ac], ap + (size_t)64 * K);
        const float* bp = &B[(size_t)(k0 + br) * N + n0 + bc];
        cpa16(&Bs[s][br][bc], bp);
        cpa16(&Bs[s][br + 8][bc], bp + (size_t)8 * N);
        CP_COMMIT();
    }

    for (int kt = 0; kt < KT; kt++) {
        CP_WAIT(STAGES - 2);
        __syncthreads();

        const int nf = kt + STAGES - 1;
        if (nf < KT) {
            const int s = nf % STAGES;
            const int k0 = nf * 16;
            const float* ap = &A[(size_t)(m0 + ar) * K + k0 + ac];
            cpa16(&As[s][ar][ac], ap);
            cpa16(&As[s][ar + 64][ac], ap + (size_t)64 * K);
            const float* bp = &B[(size_t)(k0 + br) * N + n0 + bc];
            cpa16(&Bs[s][br][bc], bp);
            cpa16(&Bs[s][br + 8][bc], bp + (size_t)8 * N);
        }
        CP_COMMIT();

        const int cur = kt % STAGES;
        #pragma unroll
        for (int ks = 0; ks < 2; ks++) {
            const int k8 = ks * 8;
            uint32_t af[2][4];
            #pragma unroll
            for (int im = 0; im < 2; im++) {
                const int m = warp_m * 32 + im * 16 + lr;
                af[im][0] = F2U(As[cur][m][k8 + lc]);
                af[im][1] = F2U(As[cur][m + 8][k8 + lc]);
                af[im][2] = F2U(As[cur][m][k8 + lc + 4]);
                af[im][3] = F2U(As[cur][m + 8][k8 + lc + 4]);
            }
            #pragma unroll
            for (int jn = 0; jn < 8; jn++) {
                const int n = warp_n * 64 + jn * 8 + lr;
                uint32_t bf0 = F2U(Bs[cur][k8 + lc][n]);
                uint32_t bf1 = F2U(Bs[cur][k8 + lc + 4][n]);
                #pragma unroll
                for (int im = 0; im < 2; im++)
                    mma8(acc[im][jn], af[im], bf0, bf1);
            }
        }
    }

    #pragma unroll
    for (int im = 0; im < 2; im++)
        #pragma unroll
        for (int jn = 0; jn < 8; jn++) {
            const int row = m0 + warp_m * 32 + im * 16 + lr;
            const int col = n0 + warp_n * 64 + jn * 8 + lc * 2;
            const float sc = (col < ncut) ? scale0 : scale1;
            const float bb0 = bias[col], bb1 = bias[col + 1];
            float v00 = sc * (acc[im][jn][0] + bb0);
            float v01 = sc * (acc[im][jn][1] + bb1);
            float v10 = sc * (acc[im][jn][2] + bb0);
            float v11 = sc * (acc[im][jn][3] + bb1);
            if (round_out) { v00 = f2tf(v00); v01 = f2tf(v01); v10 = f2tf(v10); v11 = f2tf(v11); }
            *(float2*)&C[(size_t)row * N + col] = make_float2(v00, v01);
            *(float2*)&C[(size_t)(row + 8) * N + col] = make_float2(v10, v11);
        }
}

// ---------------- pass 1: column softmax stats (exp2 domain) ----------------
__global__ __launch_bounds__(256, 2) void stats_pass(
    const float* __restrict__ QKV,
    float* __restrict__ gm, float* __restrict__ gzi)
{
    extern __shared__ float sm[];
    float (*Ks)[72] = (float(*)[72])sm;                       // [128][72]
    float (*Qs)[64][72] = (float(*)[64][72])(sm + 128 * 72);  // [2][64][72]

    const int g = blockIdx.y;
    const int b = g >> 5, hq = g & 31, h = hq >> 2;
    const int Tb = blockIdx.x;
    const int T0 = Tb * 128;

    const int tid = threadIdx.x;
    const int lane = tid & 31, w = tid >> 5;
    const int lr = lane >> 2, lc = lane & 3;
    const int r = tid >> 4, c = (tid & 15) * 4;

    const float* Kbase = QKV + 2048 + h * HDn;
    const float* Qbase = QKV + hq * HDn;

    #pragma unroll
    for (int p = 0; p < 8; p++) {
        const int row = p * 16 + r;
        *(float4*)&Ks[row][c] =
            *(const float4*)&Kbase[(size_t)(b * Sn + T0 + row) * QKVW + c];
    }

    const int tb0 = 2 * Tb;
    #pragma unroll
    for (int p = 0; p < 4; p++) {
        const int row = p * 16 + r;
        cpa16(&Qs[0][row][c], &Qbase[(size_t)(b * Sn + tb0 * 64 + row) * QKVW + c]);
    }
    CP_COMMIT();

    const int Trow0 = T0 + w * 16 + lr;
    const int Trow1 = Trow0 + 8;

    float m0 = NEGBIG, z0 = 0.f, m1 = NEGBIG, z1 = 0.f;

    for (int tb = tb0; tb < NTB64; tb++) {
        const int cur = (tb - tb0) & 1;
        __syncthreads();
        if (tb + 1 < NTB64) {
            #pragma unroll
            for (int p = 0; p < 4; p++) {
                const int row = p * 16 + r;
                cpa16(&Qs[cur ^ 1][row][c],
                      &Qbase[(size_t)(b * Sn + (tb + 1) * 64 + row) * QKVW + c]);
            }
        }
        CP_COMMIT();
        CP_WAIT(1);
        __syncthreads();

        float acc[8][4];
        #pragma unroll
        for (int j = 0; j < 8; j++)
            #pragma unroll
            for (int q = 0; q < 4; q++) acc[j][q] = 0.f;

        #pragma unroll
        for (int ks = 0; ks < 8; ks++) {
            const int k8 = ks * 8;
            uint32_t af[4];
            const float2 a0p = *(const float2*)&Ks[w * 16 + lr][k8 + 2 * lc];
            const float2 a1p = *(const float2*)&Ks[w * 16 + 8 + lr][k8 + 2 * lc];
            af[0] = F2U(a0p.x); af[2] = F2U(a0p.y);
            af[1] = F2U(a1p.x); af[3] = F2U(a1p.y);
            #pragma unroll
            for (int jn = 0; jn < 8; jn++) {
                const float2 bp = *(const float2*)&Qs[cur][jn * 8 + lr][k8 + 2 * lc];
                mma8(acc[jn], af, F2U(bp.x), F2U(bp.y));
            }
        }

        if (tb > tb0 + 1) {
            float tm0 = NEGBIG, tm1 = NEGBIG;
            #pragma unroll
            for (int jn = 0; jn < 8; jn++) {
                tm0 = fmaxf(tm0, fmaxf(acc[jn][0], acc[jn][1]));
                tm1 = fmaxf(tm1, fmaxf(acc[jn][2], acc[jn][3]));
            }
            const float nm0 = fmaxf(m0, tm0);
            const float nm1 = fmaxf(m1, tm1);
            float s0 = 0.f, s1 = 0.f;
            #pragma unroll
            for (int jn = 0; jn < 8; jn++) {
                s0 += fex2(acc[jn][0] - nm0) + fex2(acc[jn][1] - nm0);
                s1 += fex2(acc[jn][2] - nm1) + fex2(acc[jn][3] - nm1);
            }
            z0 = z0 * fex2(m0 - nm0) + s0; m0 = nm0;
            z1 = z1 * fex2(m1 - nm1) + s1; m1 = nm1;
        } else {
            const int tbase = tb * 64 + lc * 2;
            float tm0 = NEGBIG, tm1 = NEGBIG;
            float va[8][4];
            #pragma unroll
            for (int jn = 0; jn < 8; jn++) {
                const int tcol = tbase + jn * 8;
                va[jn][0] = (tcol     >= Trow0) ? acc[jn][0] : NEGBIG;
                va[jn][1] = (tcol + 1 >= Trow0) ? acc[jn][1] : NEGBIG;
                va[jn][2] = (tcol     >= Trow1) ? acc[jn][2] : NEGBIG;
                va[jn][3] = (tcol + 1 >= Trow1) ? acc[jn][3] : NEGBIG;
                tm0 = fmaxf(tm0, fmaxf(va[jn][0], va[jn][1]));
                tm1 = fmaxf(tm1, fmaxf(va[jn][2], va[jn][3]));
            }
            const float nm0 = fmaxf(m0, tm0);
            const float nm1 = fmaxf(m1, tm1);
            float s0 = 0.f, s1 = 0.f;
            #pragma unroll
            for (int jn = 0; jn < 8; jn++) {
                s0 += fex2(va[jn][0] - nm0) + fex2(va[jn][1] - nm0);
                s1 += fex2(va[jn][2] - nm1) + fex2(va[jn][3] - nm1);
            }
            z0 = z0 * fex2(m0 - nm0) + s0; m0 = nm0;
            z1 = z1 * fex2(m1 - nm1) + s1; m1 = nm1;
        }
    }

    #pragma unroll
    for (int off = 1; off < 4; off <<= 1) {
        float mo = __shfl_xor_sync(0xffffffffu, m0, off);
        float zo = __shfl_xor_sync(0xffffffffu, z0, off);
        float mn = fmaxf(m0, mo);
        z0 = z0 * fex2(m0 - mn) + zo * fex2(mo - mn); m0 = mn;
        mo = __shfl_xor_sync(0xffffffffu, m1, off);
        zo = __shfl_xor_sync(0xffffffffu, z1, off);
        mn = fmaxf(m1, mo);
        z1 = z1 * fex2(m1 - mn) + zo * fex2(mo - mn); m1 = mn;
    }
    if (lc == 0) {
        gm[g * Sn + Trow0] = m0;  gzi[g * Sn + Trow0] = 1.0f / z0;
        gm[g * Sn + Trow1] = m1;  gzi[g * Sn + Trow1] = 1.0f / z1;
    }
}
#define STATS_SMEM ((128 * 72 + 2 * 64 * 72) * 4)

// ---------------- pass 2: register-P flash; V transposed for float2 b-frags ----------------
__global__ __launch_bounds__(256, 2) void out_pass(
    const float* __restrict__ QKV, const float* __restrict__ vT,
    const float* __restrict__ gm, const float* __restrict__ gzi,
    float* __restrict__ O)
{
    extern __shared__ float sm[];
    float (*Qs)[72] = (float(*)[72])sm;                              // [128][72]
    float (*Ks)[64][72] = (float(*)[64][72])(sm + 128 * 72);         // [2][64][72]
    float (*Vt)[64][68] = (float(*)[64][68])(sm + 128 * 72 + 2 * 64 * 72); // [2][64 d][68 T]
    float* s_st = sm + 128 * 72 + 2 * 64 * 72 + 2 * 64 * 68;         // [2][128]

    const int g = blockIdx.y;
    const int b = g >> 5, hq = g & 31, h = hq >> 2;
    const int tblk = (NTB128 - 1) - blockIdx.x;
    const int t0 = tblk * 128;

    const int tid = threadIdx.x;
    const int lane = tid & 31, w = tid >> 5;     // warp owns t rows w*16 .. w*16+15
    const int lr = lane >> 2, lc = lane & 3;
    const int r = tid >> 4, c = (tid & 15) * 4;
    const int vr = tid >> 2, vc = (tid & 3) * 16;   // V tile: row d=vr, 16-float segment

    const float* Qbase = QKV + hq * HDn;
    const float* Kbase = QKV + 2048 + h * HDn;
    const float* Vtb = vT + (size_t)(b * 512 + h * HDn) * Sn;   // rows d, cols T

    #pragma unroll
    for (int p = 0; p < 8; p++) {
        const int row = p * 16 + r;
        *(float4*)&Qs[row][c] =
            *(const float4*)&Qbase[(size_t)(b * Sn + t0 + row) * QKVW + c];
    }

    // prologue: tile 0 (K + V + stats) -> buf 0
    #pragma unroll
    for (int p = 0; p < 4; p++) {
        const int row = p * 16 + r;
        cpa16(&Ks[0][row][c], &Kbase[(size_t)(b * Sn + row) * QKVW + c]);
    }
    #pragma unroll
    for (int q = 0; q < 4; q++)
        cpa16(&Vt[0][vr][vc + q * 4], &Vtb[(size_t)vr * Sn + vc + q * 4]);
    if (tid < 16)      cpa16(&s_st[tid * 4],             &gm[g * Sn + tid * 4]);
    else if (tid < 32) cpa16(&s_st[64 + (tid - 16) * 4], &gzi[g * Sn + (tid - 16) * 4]);
    CP_COMMIT();

    float acc2[8][4];
    #pragma unroll
    for (int j = 0; j < 8; j++)
        #pragma unroll
        for (int q = 0; q < 4; q++) acc2[j][q] = 0.f;

    const int trg0 = t0 + w * 16 + lr;
    const int trg1 = trg0 + 8;

    const int nT = 2 * tblk + 2;
    for (int Tb = 0; Tb < nT; Tb++) {
        const int T0 = Tb * 64;
        const int cur = Tb & 1;

        __syncthreads();
        if (Tb + 1 < nT) {
            const int Tn = (Tb + 1) * 64;
            const int nxt = cur ^ 1;
            #pragma unroll
            for (int p = 0; p < 4; p++) {
                const int row = p * 16 + r;
                cpa16(&Ks[nxt][row][c], &Kbase[(size_t)(b * Sn + Tn + row) * QKVW + c]);
            }
            #pragma unroll
            for (int q = 0; q < 4; q++)
                cpa16(&Vt[nxt][vr][vc + q * 4], &Vtb[(size_t)vr * Sn + Tn + vc + q * 4]);
            if (tid < 16)      cpa16(&s_st[nxt * 128 + tid * 4],             &gm[g * Sn + Tn + tid * 4]);
            else if (tid < 32) cpa16(&s_st[nxt * 128 + 64 + (tid - 16) * 4], &gzi[g * Sn + Tn + (tid - 16) * 4]);
        }
        CP_COMMIT();
        CP_WAIT(1);
        __syncthreads();

        // stage 1: S = Q . K
        float acc1[8][4];
        #pragma unroll
        for (int j = 0; j < 8; j++)
            #pragma unroll
            for (int q = 0; q < 4; q++) acc1[j][q] = 0.f;

        #pragma unroll
        for (int ks = 0; ks < 8; ks++) {
            const int k8 = ks * 8;
            uint32_t af[4];
            const float2 q0 = *(const float2*)&Qs[w * 16 + lr][k8 + 2 * lc];
            const float2 q1 = *(const float2*)&Qs[w * 16 + 8 + lr][k8 + 2 * lc];
            af[0] = F2U(q0.x); af[2] = F2U(q0.y);
            af[1] = F2U(q1.x); af[3] = F2U(q1.y);
            #pragma unroll
            for (int jn = 0; jn < 8; jn++) {
                const float2 kp = *(const float2*)&Ks[cur][jn * 8 + lr][k8 + 2 * lc];
                mma8(acc1[jn], af, F2U(kp.x), F2U(kp.y));
            }
        }

        // softmax apply in registers -> P fragments
        const float* smv = &s_st[cur * 128];
        const bool diag = (Tb >= 2 * tblk);
        #pragma unroll
        for (int jn = 0; jn < 8; jn++) {
            const int Tcol = jn * 8 + 2 * lc;
            const int Tg = T0 + Tcol;
            const float2 mm = *(const float2*)&smv[Tcol];
            const float2 zz = *(const float2*)&smv[64 + Tcol];
            float p00 = fex2(acc1[jn][0] - mm.x) * zz.x;
            float p01 = fex2(acc1[jn][1] - mm.y) * zz.y;
            float p10 = fex2(acc1[jn][2] - mm.x) * zz.x;
            float p11 = fex2(acc1[jn][3] - mm.y) * zz.y;
            if (diag) {
                if (trg0 < Tg)     p00 = 0.f;
                if (trg0 < Tg + 1) p01 = 0.f;
                if (trg1 < Tg)     p10 = 0.f;
                if (trg1 < Tg + 1) p11 = 0.f;
            }
            acc1[jn][0] = f2tf(p00);
            acc1[jn][1] = f2tf(p01);
            acc1[jn][2] = f2tf(p10);
            acc1[jn][3] = f2tf(p11);
        }

        // stage 2: O += P @ V  (b-fragments via float2 from transposed V)
        #pragma unroll
        for (int kt = 0; kt < 8; kt++) {
            uint32_t af[4];
            af[0] = F2U(acc1[kt][0]);
            af[1] = F2U(acc1[kt][2]);
            af[2] = F2U(acc1[kt][1]);
            af[3] = F2U(acc1[kt][3]);
            const int krow = kt * 8 + 2 * lc;
            #pragma unroll
            for (int dn = 0; dn < 8; dn++) {
                const int d = dn * 8 + lr;
                const float2 vv = *(const float2*)&Vt[cur][d][krow];
                mma8(acc2[dn], af, F2U(vv.x), F2U(vv.y));
            }
        }
    }

    #pragma unroll
    for (int dn = 0; dn < 8; dn++) {
        const int col = hq * HDn + dn * 8 + lc * 2;
        *(float2*)&O[(size_t)(b * Sn + trg0) * (HQn * HDn) + col] =
            make_float2(f2tf(acc2[dn][0]), f2tf(acc2[dn][1]));
        *(float2*)&O[(size_t)(b * Sn + trg1) * (HQn * HDn) + col] =
            make_float2(f2tf(acc2[dn][2]), f2tf(acc2[dn][3]));
    }
}
#define OUT_SMEM ((128 * 72 + 2 * 64 * 72 + 2 * 64 * 68 + 256) * 4)

// ---------------- launch ----------------
extern "C" void kernel_launch(void* const* d_in, const int* in_sizes, int n_in,
                              void* d_out, int out_size) {
    const float* x    = (const float*)d_in[0];
    const float* ln_g = (const float*)d_in[1];
    const float* ln_b = (const float*)d_in[2];
    const float* Wq   = (const float*)d_in[3];
    const float* bq   = (const float*)d_in[4];
    const float* Wk   = (const float*)d_in[5];
    const float* bk   = (const float*)d_in[6];
    const float* Wv   = (const float*)d_in[7];
    const float* bv   = (const float*)d_in[8];
    const float* Wo   = (const float*)d_in[9];
    const float* bo   = (const float*)d_in[10];
    float* out = (float*)d_out;

    float *xn, *qkv, *wf, *bf, *wo, *attn, *vt, *m, *zi;
    cudaGetSymbolAddress((void**)&xn,   g_xn);
    cudaGetSymbolAddress((void**)&qkv,  g_qkv);
    cudaGetSymbolAddress((void**)&wf,   g_wf);
    cudaGetSymbolAddress((void**)&bf,   g_bf);
    cudaGetSymbolAddress((void**)&wo,   g_wo);
    cudaGetSymbolAddress((void**)&attn, g_attn);
    cudaGetSymbolAddress((void**)&vt,   g_vt);
    cudaGetSymbolAddress((void**)&m,    g_m);
    cudaGetSymbolAddress((void**)&zi,   g_zi);

    cudaFuncSetAttribute(gemm_cp,    cudaFuncAttributeMaxDynamicSharedMemorySize, GEMM_SMEM);
    cudaFuncSetAttribute(stats_pass, cudaFuncAttributeMaxDynamicSharedMemorySize, STATS_SMEM);
    cudaFuncSetAttribute(out_pass,   cudaFuncAttributeMaxDynamicSharedMemorySize, OUT_SMEM);

    fused_pre<<<ROWS + 6144 + 4096 + 12, 256>>>(
        x, ln_g, ln_b, Wq, Wk, Wv, Wo, bq, bk, bv, xn, wf, wo, bf);

    gemm_cp<<<dim3(QKVW / 128, ROWS / 128), 256, GEMM_SMEM>>>(
        xn, wf, bf, qkv, ROWS, QKVW, Dn, QSCALE, 1.0f, 2048, 1);

    vtrans<<<dim3(Sn / 32, 512 / 32, Bn), 256>>>(qkv, vt);

    stats_pass<<<dim3(NTB128, NG), 256, STATS_SMEM>>>(qkv, m, zi);
    out_pass<<<dim3(NTB128, NG), 256, OUT_SMEM>>>(qkv, vt, m, zi, attn);

    gemm_cp<<<dim3(Dn / 128, ROWS / 128), 256, GEMM_SMEM>>>(
        attn, wo, bo, out, ROWS, Dn, HQn * HDn, 1.0f, 1.0f, 0, 0);
}

// round 13
// speedup vs baseline: 1.0866x; 1.0866x over previous
#include <cuda_runtime.h>
#include <cuda_bf16.h>
#include <cstdint>
#include <math.h>

#define Bn 2
#define Sn 2048
#define Dn 2048
#define HQn 32
#define HKVn 8
#define HDn 64
#define ROWS (Bn * Sn)      // 4096
#define NG   (Bn * HQn)     // 64 attention "heads"
#define NTB64 (Sn / 64)     // 32
#define NTB128 (Sn / 128)   // 16
#define QKVW 3072           // fused q|k|v width
#define QSCALE 0.18033688011112042f   // 0.125 * log2(e)

// ---------------- scratch ----------------
__device__ float g_xn[ROWS * Dn];
__device__ float g_qkv[(size_t)ROWS * QKVW];
__device__ float g_wf[Dn * QKVW];
__device__ float g_bf[QKVW];
__device__ float g_wo[Dn * Dn];
__device__ float g_attn[ROWS * (HQn * HDn)];
__device__ float g_gl[NG * Sn];                    // m + log2(Z) per key column

// ---------------- helpers ----------------
__device__ __forceinline__ float f2tf(float x) {
    uint32_t r;
    asm("cvt.rna.tf32.f32 %0, %1;" : "=r"(r) : "f"(x));
    return __uint_as_float(r);
}
__device__ __forceinline__ float4 cvt4(float4 v) {
    v.x = f2tf(v.x); v.y = f2tf(v.y); v.z = f2tf(v.z); v.w = f2tf(v.w);
    return v;
}
__device__ __forceinline__ float fex2(float x) {
    float r;
    asm("ex2.approx.ftz.f32 %0, %1;" : "=f"(r) : "f"(x));
    return r;
}
__device__ __forceinline__ float flg2(float x) {
    float r;
    asm("lg2.approx.ftz.f32 %0, %1;" : "=f"(r) : "f"(x));
    return r;
}
__device__ __forceinline__ void mma8(float* c, const uint32_t* a, uint32_t b0, uint32_t b1) {
    asm volatile(
        "mma.sync.aligned.m16n8k8.row.col.f32.tf32.tf32.f32 "
        "{%0,%1,%2,%3}, {%4,%5,%6,%7}, {%8,%9}, {%0,%1,%2,%3};"
        : "+f"(c[0]), "+f"(c[1]), "+f"(c[2]), "+f"(c[3])
        : "r"(a[0]), "r"(a[1]), "r"(a[2]), "r"(a[3]), "r"(b0), "r"(b1));
}
__device__ __forceinline__ void cpa16(void* dst_smem, const void* src) {
    uint32_t d = (uint32_t)__cvta_generic_to_shared(dst_smem);
    asm volatile("cp.async.cg.shared.global [%0], [%1], 16;" :: "r"(d), "l"(src));
}
#define CP_COMMIT() asm volatile("cp.async.commit_group;")
#define CP_WAIT(n)  asm volatile("cp.async.wait_group %0;" :: "n"(n))
#define F2U(x) __float_as_uint(x)
#define NEGBIG (-1e30f)

// ---------------- fused pre: LN + weight/bias prep ----------------
__global__ __launch_bounds__(256) void fused_pre(
    const float* __restrict__ x, const float* __restrict__ gamma,
    const float* __restrict__ beta,
    const float* __restrict__ Wq, const float* __restrict__ Wk,
    const float* __restrict__ Wv, const float* __restrict__ Wo,
    const float* __restrict__ bq, const float* __restrict__ bk,
    const float* __restrict__ bv,
    float* __restrict__ xn, float* __restrict__ Wf,
    float* __restrict__ Wr, float* __restrict__ bf)
{
    const int blk = blockIdx.x;
    const int tid = threadIdx.x;

    if (blk < ROWS) {
        const int row = blk;
        const float* xr = x + (size_t)row * Dn;
        float* outr = xn + (size_t)row * Dn;
        __shared__ float red[256];

        float s = 0.f;
        for (int c = tid; c < Dn; c += 256) s += xr[c];
        red[tid] = s; __syncthreads();
        for (int off = 128; off > 0; off >>= 1) {
            if (tid < off) red[tid] += red[tid + off];
            __syncthreads();
        }
        const float mu = red[0] * (1.0f / Dn);
        __syncthreads();

        float v = 0.f;
        for (int c = tid; c < Dn; c += 256) { float d = xr[c] - mu; v += d * d; }
        red[tid] = v; __syncthreads();
        for (int off = 128; off > 0; off >>= 1) {
            if (tid < off) red[tid] += red[tid + off];
            __syncthreads();
        }
        const float rstd = rsqrtf(red[0] * (1.0f / Dn) + 1e-5f);
        __syncthreads();

        for (int c = tid; c < Dn; c += 256)
            outr[c] = f2tf((xr[c] - mu) * rstd * gamma[c] + beta[c]);
    } else if (blk < ROWS + 6144) {
        const int idx = ((blk - ROWS) * 256 + tid) * 4;
        const int row = idx / QKVW, col = idx % QKVW;
        const float* src;
        if (col < 2048)      src = &Wq[(size_t)row * 2048 + col];
        else if (col < 2560) src = &Wk[(size_t)row * 512 + col - 2048];
        else                 src = &Wv[(size_t)row * 512 + col - 2560];
        *(float4*)&Wf[idx] = cvt4(*(const float4*)src);
    } else if (blk < ROWS + 6144 + 4096) {
        const int idx = ((blk - ROWS - 6144) * 256 + tid) * 4;
        *(float4*)&Wr[idx] = cvt4(*(const float4*)&Wo[idx]);
    } else {
        const int col = (blk - ROWS - 6144 - 4096) * 256 + tid;
        if (col < QKVW)
            bf[col] = col < 2048 ? bq[col] : (col < 2560 ? bk[col - 2048] : bv[col - 2560]);
    }
}

// ---------------- cp.async 3-stage tf32 GEMM ----------------
#define STAGES 3
#define GEMM_SMEM (STAGES * (128 * 20 + 16 * 136) * 4)

__global__ __launch_bounds__(256, 2) void gemm_cp(
    const float* __restrict__ A, const float* __restrict__ B,
    const float* __restrict__ bias, float* __restrict__ C,
    int M, int N, int K, float scale0, float scale1, int ncut, int round_out)
{
    extern __shared__ float sm[];
    float (*As)[128][20] = (float(*)[128][20])sm;
    float (*Bs)[16][136] = (float(*)[16][136])(sm + STAGES * 128 * 20);

    const int tid = threadIdx.x;
    const int lane = tid & 31, wid = tid >> 5;
    const int warp_m = wid & 3, warp_n = wid >> 2;
    const int m0 = blockIdx.y * 128, n0 = blockIdx.x * 128;

    const int ar = tid >> 2, ac = (tid & 3) * 4;
    const int br = tid >> 5, bc = (tid & 31) * 4;
    const int lr = lane >> 2, lc = lane & 3;

    const int KT = K / 16;

    float acc[2][8][4];
    #pragma unroll
    for (int i = 0; i < 2; i++)
        #pragma unroll
        for (int j = 0; j < 8; j++)
            #pragma unroll
            for (int q = 0; q < 4; q++) acc[i][j][q] = 0.f;

    #pragma unroll
    for (int s = 0; s < STAGES - 1; s++) {
        const int k0 = s * 16;
        const float* ap = &A[(size_t)(m0 + ar) * K + k0 + ac];
        cpa16(&As[s][ar][ac], ap);
        cpa16(&As[s][ar + 64][ac], ap + (size_t)64 * K);
        const float* bp = &B[(size_t)(k0 + br) * N + n0 + bc];
        cpa16(&Bs[s][br][bc], bp);
        cpa16(&Bs[s][br + 8][bc], bp + (size_t)8 * N);
        CP_COMMIT();
    }

    for (int kt = 0; kt < KT; kt++) {
        CP_WAIT(STAGES - 2);
        __syncthreads();

        const int nf = kt + STAGES - 1;
        if (nf < KT) {
            const int s = nf % STAGES;
            const int k0 = nf * 16;
            const float* ap = &A[(size_t)(m0 + ar) * K + k0 + ac];
            cpa16(&As[s][ar][ac], ap);
            cpa16(&As[s][ar + 64][ac], ap + (size_t)64 * K);
            const float* bp = &B[(size_t)(k0 + br) * N + n0 + bc];
            cpa16(&Bs[s][br][bc], bp);
            cpa16(&Bs[s][br + 8][bc], bp + (size_t)8 * N);
        }
        CP_COMMIT();

        const int cur = kt % STAGES;
        #pragma unroll
        for (int ks = 0; ks < 2; ks++) {
            const int k8 = ks * 8;
            uint32_t af[2][4];
            #pragma unroll
            for (int im = 0; im < 2; im++) {
                const int m = warp_m * 32 + im * 16 + lr;
                af[im][0] = F2U(As[cur][m][k8 + lc]);
                af[im][1] = F2U(As[cur][m + 8][k8 + lc]);
                af[im][2] = F2U(As[cur][m][k8 + lc + 4]);
                af[im][3] = F2U(As[cur][m + 8][k8 + lc + 4]);
            }
            #pragma unroll
            for (int jn = 0; jn < 8; jn++) {
                const int n = warp_n * 64 + jn * 8 + lr;
                uint32_t bf0 = F2U(Bs[cur][k8 + lc][n]);
                uint32_t bf1 = F2U(Bs[cur][k8 + lc + 4][n]);
                #pragma unroll
                for (int im = 0; im < 2; im++)
                    mma8(acc[im][jn], af[im], bf0, bf1);
            }
        }
    }

    #pragma unroll
    for (int im = 0; im < 2; im++)
        #pragma unroll
        for (int jn = 0; jn < 8; jn++) {
            const int row = m0 + warp_m * 32 + im * 16 + lr;
            const int col = n0 + warp_n * 64 + jn * 8 + lc * 2;
            const float sc = (col < ncut) ? scale0 : scale1;
            const float bb0 = bias[col], bb1 = bias[col + 1];
            float v00 = sc * (acc[im][jn][0] + bb0);
            float v01 = sc * (acc[im][jn][1] + bb1);
            float v10 = sc * (acc[im][jn][2] + bb0);
            float v11 = sc * (acc[im][jn][3] + bb1);
            if (round_out) { v00 = f2tf(v00); v01 = f2tf(v01); v10 = f2tf(v10); v11 = f2tf(v11); }
            *(float2*)&C[(size_t)row * N + col] = make_float2(v00, v01);
            *(float2*)&C[(size_t)(row + 8) * N + col] = make_float2(v10, v11);
        }
}

// ---------------- pass 1: column softmax stats -> gl = m + log2(Z) ----------------
__global__ __launch_bounds__(256, 3) void stats_pass(
    const float* __restrict__ QKV, float* __restrict__ ggl)
{
    extern __shared__ float sm[];
    float (*Ks)[72] = (float(*)[72])sm;                       // [128][72]
    float (*Qs)[64][72] = (float(*)[64][72])(sm + 128 * 72);  // [2][64][72]

    const int g = blockIdx.y;
    const int b = g >> 5, hq = g & 31, h = hq >> 2;
    const int Tb = blockIdx.x;
    const int T0 = Tb * 128;

    const int tid = threadIdx.x;
    const int lane = tid & 31, w = tid >> 5;
    const int lr = lane >> 2, lc = lane & 3;
    const int r = tid >> 4, c = (tid & 15) * 4;

    const float* Kbase = QKV + 2048 + h * HDn;
    const float* Qbase = QKV + hq * HDn;

    #pragma unroll
    for (int p = 0; p < 8; p++) {
        const int row = p * 16 + r;
        *(float4*)&Ks[row][c] =
            *(const float4*)&Kbase[(size_t)(b * Sn + T0 + row) * QKVW + c];
    }

    const int tb0 = 2 * Tb;
    #pragma unroll
    for (int p = 0; p < 4; p++) {
        const int row = p * 16 + r;
        cpa16(&Qs[0][row][c], &Qbase[(size_t)(b * Sn + tb0 * 64 + row) * QKVW + c]);
    }
    CP_COMMIT();

    const int Trow0 = T0 + w * 16 + lr;
    const int Trow1 = Trow0 + 8;

    float m0 = NEGBIG, z0 = 0.f, m1 = NEGBIG, z1 = 0.f;

    for (int tb = tb0; tb < NTB64; tb++) {
        const int cur = (tb - tb0) & 1;
        __syncthreads();
        if (tb + 1 < NTB64) {
            #pragma unroll
            for (int p = 0; p < 4; p++) {
                const int row = p * 16 + r;
                cpa16(&Qs[cur ^ 1][row][c],
                      &Qbase[(size_t)(b * Sn + (tb + 1) * 64 + row) * QKVW + c]);
            }
        }
        CP_COMMIT();
        CP_WAIT(1);
        __syncthreads();

        float acc[8][4];
        #pragma unroll
        for (int j = 0; j < 8; j++)
            #pragma unroll
            for (int q = 0; q < 4; q++) acc[j][q] = 0.f;

        #pragma unroll
        for (int ks = 0; ks < 8; ks++) {
            const int k8 = ks * 8;
            uint32_t af[4];
            const float2 a0p = *(const float2*)&Ks[w * 16 + lr][k8 + 2 * lc];
            const float2 a1p = *(const float2*)&Ks[w * 16 + 8 + lr][k8 + 2 * lc];
            af[0] = F2U(a0p.x); af[2] = F2U(a0p.y);
            af[1] = F2U(a1p.x); af[3] = F2U(a1p.y);
            #pragma unroll
            for (int jn = 0; jn < 8; jn++) {
                const float2 bp = *(const float2*)&Qs[cur][jn * 8 + lr][k8 + 2 * lc];
                mma8(acc[jn], af, F2U(bp.x), F2U(bp.y));
            }
        }

        if (tb > tb0 + 1) {
            float tm0 = NEGBIG, tm1 = NEGBIG;
            #pragma unroll
            for (int jn = 0; jn < 8; jn++) {
                tm0 = fmaxf(tm0, fmaxf(acc[jn][0], acc[jn][1]));
                tm1 = fmaxf(tm1, fmaxf(acc[jn][2], acc[jn][3]));
            }
            const float nm0 = fmaxf(m0, tm0);
            const float nm1 = fmaxf(m1, tm1);
            float s0 = 0.f, s1 = 0.f;
            #pragma unroll
            for (int jn = 0; jn < 8; jn++) {
                s0 += fex2(acc[jn][0] - nm0) + fex2(acc[jn][1] - nm0);
                s1 += fex2(acc[jn][2] - nm1) + fex2(acc[jn][3] - nm1);
            }
            z0 = z0 * fex2(m0 - nm0) + s0; m0 = nm0;
            z1 = z1 * fex2(m1 - nm1) + s1; m1 = nm1;
        } else {
            const int tbase = tb * 64 + lc * 2;
            float tm0 = NEGBIG, tm1 = NEGBIG;
            float va[8][4];
            #pragma unroll
            for (int jn = 0; jn < 8; jn++) {
                const int tcol = tbase + jn * 8;
                va[jn][0] = (tcol     >= Trow0) ? acc[jn][0] : NEGBIG;
                va[jn][1] = (tcol + 1 >= Trow0) ? acc[jn][1] : NEGBIG;
                va[jn][2] = (tcol     >= Trow1) ? acc[jn][2] : NEGBIG;
                va[jn][3] = (tcol + 1 >= Trow1) ? acc[jn][3] : NEGBIG;
                tm0 = fmaxf(tm0, fmaxf(va[jn][0], va[jn][1]));
                tm1 = fmaxf(tm1, fmaxf(va[jn][2], va[jn][3]));
            }
            const float nm0 = fmaxf(m0, tm0);
            const float nm1 = fmaxf(m1, tm1);
            float s0 = 0.f, s1 = 0.f;
            #pragma unroll
            for (int jn = 0; jn < 8; jn++) {
                s0 += fex2(va[jn][0] - nm0) + fex2(va[jn][1] - nm0);
                s1 += fex2(va[jn][2] - nm1) + fex2(va[jn][3] - nm1);
            }
            z0 = z0 * fex2(m0 - nm0) + s0; m0 = nm0;
            z1 = z1 * fex2(m1 - nm1) + s1; m1 = nm1;
        }
    }

    #pragma unroll
    for (int off = 1; off < 4; off <<= 1) {
        float mo = __shfl_xor_sync(0xffffffffu, m0, off);
        float zo = __shfl_xor_sync(0xffffffffu, z0, off);
        float mn = fmaxf(m0, mo);
        z0 = z0 * fex2(m0 - mn) + zo * fex2(mo - mn); m0 = mn;
        mo = __shfl_xor_sync(0xffffffffu, m1, off);
        zo = __shfl_xor_sync(0xffffffffu, z1, off);
        mn = fmaxf(m1, mo);
        z1 = z1 * fex2(m1 - mn) + zo * fex2(mo - mn); m1 = mn;
    }
    if (lc == 0) {
        ggl[g * Sn + Trow0] = m0 + flg2(z0);
        ggl[g * Sn + Trow1] = m1 + flg2(z1);
    }
}
#define STATS_SMEM ((128 * 72 + 2 * 64 * 72) * 4)

// ---------------- pass 2: register-P flash; warp = 16t x full 64T ----------------
// K/V/gl fully double-buffered, one cp group per iteration, 2 syncs/iter.
__global__ __launch_bounds__(256, 2) void out_pass(
    const float* __restrict__ QKV, const float* __restrict__ ggl,
    float* __restrict__ O)
{
    extern __shared__ float sm[];
    float (*Qs)[72] = (float(*)[72])sm;                              // [128][72]
    float (*Ks)[64][72] = (float(*)[64][72])(sm + 128 * 72);         // [2][64][72]
    float (*Vs)[64][68] = (float(*)[64][68])(sm + 128 * 72 + 2 * 64 * 72); // [2][64][68]
    float* s_gl = sm + 128 * 72 + 2 * 64 * 72 + 2 * 64 * 68;         // [2][64]

    const int g = blockIdx.y;
    const int b = g >> 5, hq = g & 31, h = hq >> 2;
    const int tblk = (NTB128 - 1) - blockIdx.x;
    const int t0 = tblk * 128;

    const int tid = threadIdx.x;
    const int lane = tid & 31, w = tid >> 5;     // warp owns t rows w*16 .. w*16+15
    const int lr = lane >> 2, lc = lane & 3;
    const int r = tid >> 4, c = (tid & 15) * 4;

    const float* Qbase = QKV + hq * HDn;
    const float* Kbase = QKV + 2048 + h * HDn;
    const float* Vbase = QKV + 2560 + h * HDn;

    #pragma unroll
    for (int p = 0; p < 8; p++) {
        const int row = p * 16 + r;
        *(float4*)&Qs[row][c] =
            *(const float4*)&Qbase[(size_t)(b * Sn + t0 + row) * QKVW + c];
    }

    // prologue: tile 0 (K + V + gl) -> buf 0
    #pragma unroll
    for (int p = 0; p < 4; p++) {
        const int row = p * 16 + r;
        cpa16(&Ks[0][row][c], &Kbase[(size_t)(b * Sn + row) * QKVW + c]);
        cpa16(&Vs[0][row][c], &Vbase[(size_t)(b * Sn + row) * QKVW + c]);
    }
    if (tid < 16) cpa16(&s_gl[tid * 4], &ggl[g * Sn + tid * 4]);
    CP_COMMIT();

    float acc2[8][4];
    #pragma unroll
    for (int j = 0; j < 8; j++)
        #pragma unroll
        for (int q = 0; q < 4; q++) acc2[j][q] = 0.f;

    const int trg0 = t0 + w * 16 + lr;
    const int trg1 = trg0 + 8;

    const int nT = 2 * tblk + 2;
    for (int Tb = 0; Tb < nT; Tb++) {
        const int T0 = Tb * 64;
        const int cur = Tb & 1;

        __syncthreads();                  // all warps done with buffer cur^1 (iter Tb-1)
        if (Tb + 1 < nT) {
            const int Tn = (Tb + 1) * 64;
            const int nxt = cur ^ 1;
            #pragma unroll
            for (int p = 0; p < 4; p++) {
                const int row = p * 16 + r;
                cpa16(&Ks[nxt][row][c], &Kbase[(size_t)(b * Sn + Tn + row) * QKVW + c]);
                cpa16(&Vs[nxt][row][c], &Vbase[(size_t)(b * Sn + Tn + row) * QKVW + c]);
            }
            if (tid < 16) cpa16(&s_gl[nxt * 64 + tid * 4], &ggl[g * Sn + Tn + tid * 4]);
        }
        CP_COMMIT();
        CP_WAIT(1);                       // retires cp(Tb) — prefetched one iter ago
        __syncthreads();

        // stage 1: S = Q . K  (warp: 16 t-rows x full 64 T; paired 64-bit loads)
        float acc1[8][4];
        #pragma unroll
        for (int j = 0; j < 8; j++)
            #pragma unroll
            for (int q = 0; q < 4; q++) acc1[j][q] = 0.f;

        #pragma unroll
        for (int ks = 0; ks < 8; ks++) {
            const int k8 = ks * 8;
            uint32_t af[4];
            const float2 q0 = *(const float2*)&Qs[w * 16 + lr][k8 + 2 * lc];
            const float2 q1 = *(const float2*)&Qs[w * 16 + 8 + lr][k8 + 2 * lc];
            af[0] = F2U(q0.x); af[2] = F2U(q0.y);
            af[1] = F2U(q1.x); af[3] = F2U(q1.y);
            #pragma unroll
            for (int jn = 0; jn < 8; jn++) {
                const float2 kp = *(const float2*)&Ks[cur][jn * 8 + lr][k8 + 2 * lc];
                mma8(acc1[jn], af, F2U(kp.x), F2U(kp.y));
            }
        }

        // softmax apply IN REGISTERS: p = exp2(s - gl)
        const float* smv = &s_gl[cur * 64];
        const bool diag = (Tb >= 2 * tblk);
        #pragma unroll
        for (int jn = 0; jn < 8; jn++) {
            const int Tcol = jn * 8 + 2 * lc;
            const int Tg = T0 + Tcol;
            const float2 gl = *(const float2*)&smv[Tcol];
            float p00 = fex2(acc1[jn][0] - gl.x);
            float p01 = fex2(acc1[jn][1] - gl.y);
            float p10 = fex2(acc1[jn][2] - gl.x);
            float p11 = fex2(acc1[jn][3] - gl.y);
            if (diag) {
                if (trg0 < Tg)     p00 = 0.f;
                if (trg0 < Tg + 1) p01 = 0.f;
                if (trg1 < Tg)     p10 = 0.f;
                if (trg1 < Tg + 1) p11 = 0.f;
            }
            acc1[jn][0] = f2tf(p00);
            acc1[jn][1] = f2tf(p01);
            acc1[jn][2] = f2tf(p10);
            acc1[jn][3] = f2tf(p11);
        }

        // stage 2: O += P @ V   (A = P fragments in registers; V rows k-paired)
        #pragma unroll
        for (int kt = 0; kt < 8; kt++) {
            uint32_t af[4];
            af[0] = F2U(acc1[kt][0]);
            af[1] = F2U(acc1[kt][2]);
            af[2] = F2U(acc1[kt][1]);
            af[3] = F2U(acc1[kt][3]);
            const int krow = kt * 8 + 2 * lc;
            #pragma unroll
            for (int dn = 0; dn < 8; dn++) {
                const int d = dn * 8 + lr;
                const uint32_t bf0 = F2U(Vs[cur][krow][d]);
                const uint32_t bf1 = F2U(Vs[cur][krow + 1][d]);
                mma8(acc2[dn], af, bf0, bf1);
            }
        }
    }

    #pragma unroll
    for (int dn = 0; dn < 8; dn++) {
        const int col = hq * HDn + dn * 8 + lc * 2;
        *(float2*)&O[(size_t)(b * Sn + trg0) * (HQn * HDn) + col] =
            make_float2(f2tf(acc2[dn][0]), f2tf(acc2[dn][1]));
        *(float2*)&O[(size_t)(b * Sn + trg1) * (HQn * HDn) + col] =
            make_float2(f2tf(acc2[dn][2]), f2tf(acc2[dn][3]));
    }
}
#define OUT_SMEM ((128 * 72 + 2 * 64 * 72 + 2 * 64 * 68 + 128) * 4)

// ---------------- launch ----------------
extern "C" void kernel_launch(void* const* d_in, const int* in_sizes, int n_in,
                              void* d_out, int out_size) {
    const float* x    = (const float*)d_in[0];
    const float* ln_g = (const float*)d_in[1];
    const float* ln_b = (const float*)d_in[2];
    const float* Wq   = (const float*)d_in[3];
    const float* bq   = (const float*)d_in[4];
    const float* Wk   = (const float*)d_in[5];
    const float* bk   = (const float*)d_in[6];
    const float* Wv   = (const float*)d_in[7];
    const float* bv   = (const float*)d_in[8];
    const float* Wo   = (const float*)d_in[9];
    const float* bo   = (const float*)d_in[10];
    float* out = (float*)d_out;

    float *xn, *qkv, *wf, *bf, *wo, *attn, *gl;
    cudaGetSymbolAddress((void**)&xn,   g_xn);
    cudaGetSymbolAddress((void**)&qkv,  g_qkv);
    cudaGetSymbolAddress((void**)&wf,   g_wf);
    cudaGetSymbolAddress((void**)&bf,   g_bf);
    cudaGetSymbolAddress((void**)&wo,   g_wo);
    cudaGetSymbolAddress((void**)&attn, g_attn);
    cudaGetSymbolAddress((void**)&gl,   g_gl);

    cudaFuncSetAttribute(gemm_cp,    cudaFuncAttributeMaxDynamicSharedMemorySize, GEMM_SMEM);
    cudaFuncSetAttribute(stats_pass, cudaFuncAttributeMaxDynamicSharedMemorySize, STATS_SMEM);
    cudaFuncSetAttribute(out_pass,   cudaFuncAttributeMaxDynamicSharedMemorySize, OUT_SMEM);

    fused_pre<<<ROWS + 6144 + 4096 + 12, 256>>>(
        x, ln_g, ln_b, Wq, Wk, Wv, Wo, bq, bk, bv, xn, wf, wo, bf);

    gemm_cp<<<dim3(QKVW / 128, ROWS / 128), 256, GEMM_SMEM>>>(
        xn, wf, bf, qkv, ROWS, QKVW, Dn, QSCALE, 1.0f, 2048, 1);

    stats_pass<<<dim3(NTB128, NG), 256, STATS_SMEM>>>(qkv, gl);
    out_pass<<<dim3(NTB128, NG), 256, OUT_SMEM>>>(qkv, gl, attn);

    gemm_cp<<<dim3(Dn / 128, ROWS / 128), 256, GEMM_SMEM>>>(
        attn, wo, bo, out, ROWS, Dn, HQn * HDn, 1.0f, 1.0f, 0, 0);
}

// round 14
// speedup vs baseline: 1.8210x; 1.6759x over previous
#include <cuda_runtime.h>
#include <cuda_fp16.h>
#include <cuda_bf16.h>
#include <cstdint>
#include <math.h>

#define Bn 2
#define Sn 2048
#define Dn 2048
#define HQn 32
#define HKVn 8
#define HDn 64
#define ROWS (Bn * Sn)      // 4096
#define NG   (Bn * HQn)     // 64 attention "heads"
#define NTB64 (Sn / 64)     // 32
#define NTB128 (Sn / 128)   // 16
#define QKVW 3072
#define QSCALE 0.18033688011112042f   // 0.125 * log2(e)

// ---------------- scratch ----------------
__device__ __half g_xn[ROWS * Dn];
__device__ __half g_qkv[(size_t)ROWS * QKVW];
__device__ __half g_wf[(size_t)QKVW * Dn];         // transposed [n][k]
__device__ float  g_bf[QKVW];
__device__ __half g_wo[(size_t)Dn * Dn];           // transposed [n][k]
__device__ __half g_attn[ROWS * (HQn * HDn)];
__device__ __half g_vt[(size_t)Bn * 512 * Sn];     // V transposed [b][h*64+d][T]
__device__ float  g_gl[NG * Sn];                   // m + log2(Z)

// ---------------- helpers ----------------
__device__ __forceinline__ float fex2(float x) {
    float r; asm("ex2.approx.ftz.f32 %0, %1;" : "=f"(r) : "f"(x)); return r;
}
__device__ __forceinline__ float flg2(float x) {
    float r; asm("lg2.approx.ftz.f32 %0, %1;" : "=f"(r) : "f"(x)); return r;
}
__device__ __forceinline__ uint32_t pack2h(float x, float y) {
    __half2 h = __floats2half2_rn(x, y);
    return *(uint32_t*)&h;
}
__device__ __forceinline__ void mma16(float* c, uint32_t a0, uint32_t a1, uint32_t a2,
                                      uint32_t a3, uint32_t b0, uint32_t b1) {
    asm volatile(
        "mma.sync.aligned.m16n8k16.row.col.f32.f16.f16.f32 "
        "{%0,%1,%2,%3}, {%4,%5,%6,%7}, {%8,%9}, {%0,%1,%2,%3};"
        : "+f"(c[0]), "+f"(c[1]), "+f"(c[2]), "+f"(c[3])
        : "r"(a0), "r"(a1), "r"(a2), "r"(a3), "r"(b0), "r"(b1));
}
__device__ __forceinline__ void cpa16(void* dst_smem, const void* src) {
    uint32_t d = (uint32_t)__cvta_generic_to_shared(dst_smem);
    asm volatile("cp.async.cg.shared.global [%0], [%1], 16;" :: "r"(d), "l"(src));
}
#define CP_COMMIT() asm volatile("cp.async.commit_group;")
#define CP_WAIT(n)  asm volatile("cp.async.wait_group %0;" :: "n"(n))
#define LDU32(p) (*(const uint32_t*)(p))
#define NEGBIG (-1e30f)

// ---------------- fused pre: LN + weight transpose/convert + bias ----------------
#define NB_LN   ROWS
#define NB_WQKV ((Dn / 32) * (QKVW / 32))   // 64*96 = 6144
#define NB_WO   ((Dn / 32) * (Dn / 32))     // 4096
#define NB_BIAS 12
__global__ __launch_bounds__(256) void fused_pre(
    const float* __restrict__ x, const float* __restrict__ gamma,
    const float* __restrict__ beta,
    const float* __restrict__ Wq, const float* __restrict__ Wk,
    const float* __restrict__ Wv, const float* __restrict__ Wo,
    const float* __restrict__ bq, const float* __restrict__ bk,
    const float* __restrict__ bv,
    __half* __restrict__ xn, __half* __restrict__ Wf,
    __half* __restrict__ Wr, float* __restrict__ bf)
{
    __shared__ float red[256];
    __shared__ __half tileh[32][33];
    const int blk = blockIdx.x;
    const int tid = threadIdx.x;

    if (blk < NB_LN) {
        const int row = blk;
        const float* xr = x + (size_t)row * Dn;
        __half* outr = xn + (size_t)row * Dn;

        float s = 0.f;
        for (int c = tid; c < Dn; c += 256) s += xr[c];
        red[tid] = s; __syncthreads();
        for (int off = 128; off > 0; off >>= 1) {
            if (tid < off) red[tid] += red[tid + off];
            __syncthreads();
        }
        const float mu = red[0] * (1.0f / Dn);
        __syncthreads();

        float v = 0.f;
        for (int c = tid; c < Dn; c += 256) { float d = xr[c] - mu; v += d * d; }
        red[tid] = v; __syncthreads();
        for (int off = 128; off > 0; off >>= 1) {
            if (tid < off) red[tid] += red[tid + off];
            __syncthreads();
        }
        const float rstd = rsqrtf(red[0] * (1.0f / Dn) + 1e-5f);
        __syncthreads();

        for (int c = tid; c < Dn; c += 256)
            outr[c] = __float2half((xr[c] - mu) * rstd * gamma[c] + beta[c]);
    } else if (blk < NB_LN + NB_WQKV) {
        const int tidx = blk - NB_LN;
        const int tk = tidx & 63, tn = tidx >> 6;
        const int tx = tid & 31, ty = tid >> 5;
        #pragma unroll
        for (int i = 0; i < 32; i += 8) {
            const int k = tk * 32 + ty + i;
            const int n = tn * 32 + tx;
            float val;
            if (n < 2048)      val = Wq[(size_t)k * 2048 + n];
            else if (n < 2560) val = Wk[(size_t)k * 512 + n - 2048];
            else               val = Wv[(size_t)k * 512 + n - 2560];
            tileh[ty + i][tx] = __float2half(val);
        }
        __syncthreads();
        #pragma unroll
        for (int i = 0; i < 32; i += 8) {
            const int n = tn * 32 + ty + i;
            const int k = tk * 32 + tx;
            Wf[(size_t)n * Dn + k] = tileh[tx][ty + i];
        }
    } else if (blk < NB_LN + NB_WQKV + NB_WO) {
        const int tidx = blk - NB_LN - NB_WQKV;
        const int tk = tidx & 63, tn = tidx >> 6;
        const int tx = tid & 31, ty = tid >> 5;
        #pragma unroll
        for (int i = 0; i < 32; i += 8)
            tileh[ty + i][tx] = __float2half(Wo[(size_t)(tk * 32 + ty + i) * 2048 + tn * 32 + tx]);
        __syncthreads();
        #pragma unroll
        for (int i = 0; i < 32; i += 8)
            Wr[(size_t)(tn * 32 + ty + i) * Dn + tk * 32 + tx] = tileh[tx][ty + i];
    } else {
        const int col = (blk - NB_LN - NB_WQKV - NB_WO) * 256 + tid;
        if (col < QKVW)
            bf[col] = col < 2048 ? bq[col] : (col < 2560 ? bk[col - 2048] : bv[col - 2560]);
    }
}

// ---------------- fp16 GEMM: C = scale*(A @ Bt^T + bias); A[M][K], Bt[N][K] ----------------
// BM=128, BN=128, BK=32, 3-stage cp.async, 8 warps (4x2), warp 32x64.
#define GSTAGES 3
#define GEMM_SMEM (GSTAGES * 2 * 128 * 40 * 2)

template<int HALF_OUT>
__global__ __launch_bounds__(256, 2) void gemm_f16(
    const __half* __restrict__ A, const __half* __restrict__ Bt,
    const float* __restrict__ bias, void* __restrict__ Cv,
    int M, int N, int K, float scale0, float scale1, int ncut)
{
    extern __shared__ __half smh[];
    __half (*As)[128][40] = (__half(*)[128][40])smh;
    __half (*Bs)[128][40] = (__half(*)[128][40])(smh + GSTAGES * 128 * 40);

    const int tid = threadIdx.x;
    const int lane = tid & 31, wid = tid >> 5;
    const int warp_m = wid & 3, warp_n = wid >> 2;
    const int m0 = blockIdx.y * 128, n0 = blockIdx.x * 128;
    const int lr = lane >> 2, lc = lane & 3;

    const int KT = K / 32;

    float acc[2][8][4];
    #pragma unroll
    for (int i = 0; i < 2; i++)
        #pragma unroll
        for (int j = 0; j < 8; j++)
            #pragma unroll
            for (int q = 0; q < 4; q++) acc[i][j][q] = 0.f;

    #pragma unroll
    for (int s = 0; s < GSTAGES - 1; s++) {
        const int k0 = s * 32;
        #pragma unroll
        for (int t = tid; t < 512; t += 256) {
            const int row = t >> 2, cg = (t & 3) * 8;
            cpa16(&As[s][row][cg], &A[(size_t)(m0 + row) * K + k0 + cg]);
            cpa16(&Bs[s][row][cg], &Bt[(size_t)(n0 + row) * K + k0 + cg]);
        }
        CP_COMMIT();
    }

    for (int kt = 0; kt < KT; kt++) {
        CP_WAIT(GSTAGES - 2);
        __syncthreads();

        const int nf = kt + GSTAGES - 1;
        if (nf < KT) {
            const int s = nf % GSTAGES;
            const int k0 = nf * 32;
            #pragma unroll
            for (int t = tid; t < 512; t += 256) {
                const int row = t >> 2, cg = (t & 3) * 8;
                cpa16(&As[s][row][cg], &A[(size_t)(m0 + row) * K + k0 + cg]);
                cpa16(&Bs[s][row][cg], &Bt[(size_t)(n0 + row) * K + k0 + cg]);
            }
        }
        CP_COMMIT();

        const int cur = kt % GSTAGES;
        #pragma unroll
        for (int ks = 0; ks < 2; ks++) {
            const int kb = ks * 16;
            uint32_t af[2][4];
            #pragma unroll
            for (int im = 0; im < 2; im++) {
                const int m = warp_m * 32 + im * 16 + lr;
                af[im][0] = LDU32(&As[cur][m][kb + 2 * lc]);
                af[im][1] = LDU32(&As[cur][m + 8][kb + 2 * lc]);
                af[im][2] = LDU32(&As[cur][m][kb + 2 * lc + 8]);
                af[im][3] = LDU32(&As[cur][m + 8][kb + 2 * lc + 8]);
            }
            #pragma unroll
            for (int jn = 0; jn < 8; jn++) {
                const int n = warp_n * 64 + jn * 8 + lr;
                const uint32_t b0 = LDU32(&Bs[cur][n][kb + 2 * lc]);
                const uint32_t b1 = LDU32(&Bs[cur][n][kb + 2 * lc + 8]);
                #pragma unroll
                for (int im = 0; im < 2; im++)
                    mma16(acc[im][jn], af[im][0], af[im][1], af[im][2], af[im][3], b0, b1);
            }
        }
    }

    #pragma unroll
    for (int im = 0; im < 2; im++)
        #pragma unroll
        for (int jn = 0; jn < 8; jn++) {
            const int row = m0 + warp_m * 32 + im * 16 + lr;
            const int col = n0 + warp_n * 64 + jn * 8 + lc * 2;
            const float sc = (col < ncut) ? scale0 : scale1;
            const float bb0 = bias[col], bb1 = bias[col + 1];
            const float v00 = sc * (acc[im][jn][0] + bb0);
            const float v01 = sc * (acc[im][jn][1] + bb1);
            const float v10 = sc * (acc[im][jn][2] + bb0);
            const float v11 = sc * (acc[im][jn][3] + bb1);
            if (HALF_OUT) {
                __half* C = (__half*)Cv;
                *(uint32_t*)&C[(size_t)row * N + col] = pack2h(v00, v01);
                *(uint32_t*)&C[(size_t)(row + 8) * N + col] = pack2h(v10, v11);
            } else {
                float* C = (float*)Cv;
                *(float2*)&C[(size_t)row * N + col] = make_float2(v00, v01);
                *(float2*)&C[(size_t)(row + 8) * N + col] = make_float2(v10, v11);
            }
        }
}

// ---------------- V transpose (half): qkv v-part [t][hd] -> vt [hd][t] ----------------
__global__ __launch_bounds__(256) void vtrans(
    const __half* __restrict__ QKV, __half* __restrict__ vT)
{
    __shared__ __half tile[32][33];
    const int b = blockIdx.z;
    const int hd0 = blockIdx.y * 32;
    const int t0 = blockIdx.x * 32;
    const int tx = threadIdx.x & 31, ty = threadIdx.x >> 5;

    #pragma unroll
    for (int i = 0; i < 32; i += 8)
        tile[ty + i][tx] = QKV[(size_t)(b * Sn + t0 + ty + i) * QKVW + 2560 + hd0 + tx];
    __syncthreads();
    #pragma unroll
    for (int i = 0; i < 32; i += 8)
        vT[(size_t)(b * 512 + hd0 + ty + i) * Sn + t0 + tx] = tile[tx][ty + i];
}

// ---------------- pass 1: column softmax stats -> gl = m + log2(Z) (fp16 mma) ----------------
#define STATS_SMEM ((128 * 72 + 2 * 64 * 72) * 2)
__global__ __launch_bounds__(256, 3) void stats_pass(
    const __half* __restrict__ QKV, float* __restrict__ ggl)
{
    extern __shared__ __half smh[];
    __half (*Ks)[72] = (__half(*)[72])smh;                    // [128][72]
    __half (*Qs)[64][72] = (__half(*)[64][72])(smh + 128 * 72);

    const int g = blockIdx.y;
    const int b = g >> 5, hq = g & 31, h = hq >> 2;
    const int Tb = blockIdx.x;
    const int T0 = Tb * 128;

    const int tid = threadIdx.x;
    const int lane = tid & 31, w = tid >> 5;
    const int lr = lane >> 2, lc = lane & 3;

    const __half* Kbase = QKV + 2048 + h * HDn;
    const __half* Qbase = QKV + hq * HDn;

    #pragma unroll
    for (int p = 0; p < 4; p++) {
        const int row = p * 32 + (tid >> 3);
        const int c8 = (tid & 7) * 8;
        *(float4*)&Ks[row][c8] =
            *(const float4*)&Kbase[(size_t)(b * Sn + T0 + row) * QKVW + c8];
    }

    const int tb0 = 2 * Tb;
    #pragma unroll
    for (int t = tid; t < 512; t += 256) {
        const int row = t >> 3, c8 = (t & 7) * 8;
        cpa16(&Qs[0][row][c8], &Qbase[(size_t)(b * Sn + tb0 * 64 + row) * QKVW + c8]);
    }
    CP_COMMIT();

    const int Trow0 = T0 + w * 16 + lr;
    const int Trow1 = Trow0 + 8;

    float m0 = NEGBIG, z0 = 0.f, m1 = NEGBIG, z1 = 0.f;

    for (int tb = tb0; tb < NTB64; tb++) {
        const int cur = (tb - tb0) & 1;
        __syncthreads();
        if (tb + 1 < NTB64) {
            #pragma unroll
            for (int t = tid; t < 512; t += 256) {
                const int row = t >> 3, c8 = (t & 7) * 8;
                cpa16(&Qs[cur ^ 1][row][c8],
                      &Qbase[(size_t)(b * Sn + (tb + 1) * 64 + row) * QKVW + c8]);
            }
        }
        CP_COMMIT();
        CP_WAIT(1);
        __syncthreads();

        float acc[8][4];
        #pragma unroll
        for (int j = 0; j < 8; j++)
            #pragma unroll
            for (int q = 0; q < 4; q++) acc[j][q] = 0.f;

        #pragma unroll
        for (int ks = 0; ks < 4; ks++) {
            const int kb = ks * 16;
            const uint32_t a0 = LDU32(&Ks[w * 16 + lr][kb + 2 * lc]);
            const uint32_t a1 = LDU32(&Ks[w * 16 + 8 + lr][kb + 2 * lc]);
            const uint32_t a2 = LDU32(&Ks[w * 16 + lr][kb + 2 * lc + 8]);
            const uint32_t a3 = LDU32(&Ks[w * 16 + 8 + lr][kb + 2 * lc + 8]);
            #pragma unroll
            for (int jn = 0; jn < 8; jn++) {
                const uint32_t b0 = LDU32(&Qs[cur][jn * 8 + lr][kb + 2 * lc]);
                const uint32_t b1 = LDU32(&Qs[cur][jn * 8 + lr][kb + 2 * lc + 8]);
                mma16(acc[jn], a0, a1, a2, a3, b0, b1);
            }
        }

        if (tb > tb0 + 1) {
            float tm0 = NEGBIG, tm1 = NEGBIG;
            #pragma unroll
            for (int jn = 0; jn < 8; jn++) {
                tm0 = fmaxf(tm0, fmaxf(acc[jn][0], acc[jn][1]));
                tm1 = fmaxf(tm1, fmaxf(acc[jn][2], acc[jn][3]));
            }
            const float nm0 = fmaxf(m0, tm0);
            const float nm1 = fmaxf(m1, tm1);
            float s0 = 0.f, s1 = 0.f;
            #pragma unroll
            for (int jn = 0; jn < 8; jn++) {
                s0 += fex2(acc[jn][0] - nm0) + fex2(acc[jn][1] - nm0);
                s1 += fex2(acc[jn][2] - nm1) + fex2(acc[jn][3] - nm1);
            }
            z0 = z0 * fex2(m0 - nm0) + s0; m0 = nm0;
            z1 = z1 * fex2(m1 - nm1) + s1; m1 = nm1;
        } else {
            const int tbase = tb * 64 + lc * 2;
            float tm0 = NEGBIG, tm1 = NEGBIG;
            float va[8][4];
            #pragma unroll
            for (int jn = 0; jn < 8; jn++) {
                const int tcol = tbase + jn * 8;
                va[jn][0] = (tcol     >= Trow0) ? acc[jn][0] : NEGBIG;
                va[jn][1] = (tcol + 1 >= Trow0) ? acc[jn][1] : NEGBIG;
                va[jn][2] = (tcol     >= Trow1) ? acc[jn][2] : NEGBIG;
                va[jn][3] = (tcol + 1 >= Trow1) ? acc[jn][3] : NEGBIG;
                tm0 = fmaxf(tm0, fmaxf(va[jn][0], va[jn][1]));
                tm1 = fmaxf(tm1, fmaxf(va[jn][2], va[jn][3]));
            }
            const float nm0 = fmaxf(m0, tm0);
            const float nm1 = fmaxf(m1, tm1);
            float s0 = 0.f, s1 = 0.f;
            #pragma unroll
            for (int jn = 0; jn < 8; jn++) {
                s0 += fex2(va[jn][0] - nm0) + fex2(va[jn][1] - nm0);
                s1 += fex2(va[jn][2] - nm1) + fex2(va[jn][3] - nm1);
            }
            z0 = z0 * fex2(m0 - nm0) + s0; m0 = nm0;
            z1 = z1 * fex2(m1 - nm1) + s1; m1 = nm1;
        }
    }

    #pragma unroll
    for (int off = 1; off < 4; off <<= 1) {
        float mo = __shfl_xor_sync(0xffffffffu, m0, off);
        float zo = __shfl_xor_sync(0xffffffffu, z0, off);
        float mn = fmaxf(m0, mo);
        z0 = z0 * fex2(m0 - mn) + zo * fex2(mo - mn); m0 = mn;
        mo = __shfl_xor_sync(0xffffffffu, m1, off);
        zo = __shfl_xor_sync(0xffffffffu, z1, off);
        mn = fmaxf(m1, mo);
        z1 = z1 * fex2(m1 - mn) + zo * fex2(mo - mn); m1 = mn;
    }
    if (lc == 0) {
        ggl[g * Sn + Trow0] = m0 + flg2(z0);
        ggl[g * Sn + Trow1] = m1 + flg2(z1);
    }
}

// ---------------- pass 2: register-P flash, fp16 mma, transposed V ----------------
#define OUT_SMEM ((128 * 72 + 2 * 64 * 72 + 2 * 64 * 72) * 2 + 2 * 64 * 4)
__global__ __launch_bounds__(256, 2) void out_pass(
    const __half* __restrict__ QKV, const __half* __restrict__ vT,
    const float* __restrict__ ggl, __half* __restrict__ O)
{
    extern __shared__ __half smh[];
    __half (*Qs)[72] = (__half(*)[72])smh;                           // [128][72]
    __half (*Ks)[64][72] = (__half(*)[64][72])(smh + 128 * 72);      // [2][64][72]
    __half (*Vt)[64][72] = (__half(*)[64][72])(smh + 128 * 72 + 2 * 64 * 72); // [2][64 d][72 T]
    float* s_gl = (float*)(smh + 128 * 72 + 4 * 64 * 72);            // [2][64]

    const int g = blockIdx.y;
    const int b = g >> 5, hq = g & 31, h = hq >> 2;
    const int tblk = (NTB128 - 1) - blockIdx.x;
    const int t0 = tblk * 128;

    const int tid = threadIdx.x;
    const int lane = tid & 31, w = tid >> 5;
    const int lr = lane >> 2, lc = lane & 3;

    const __half* Qbase = QKV + hq * HDn;
    const __half* Kbase = QKV + 2048 + h * HDn;
    const __half* Vtb = vT + (size_t)(b * 512 + h * HDn) * Sn;

    #pragma unroll
    for (int p = 0; p < 4; p++) {
        const int t = p * 256 + tid;
        const int row = t >> 3, c8 = (t & 7) * 8;
        *(float4*)&Qs[row][c8] =
            *(const float4*)&Qbase[(size_t)(b * Sn + t0 + row) * QKVW + c8];
    }

    // prologue: tile 0 (K + Vt + gl) -> buf 0
    #pragma unroll
    for (int t = tid; t < 512; t += 256) {
        const int row = t >> 3, c8 = (t & 7) * 8;
        cpa16(&Ks[0][row][c8], &Kbase[(size_t)(b * Sn + row) * QKVW + c8]);
        cpa16(&Vt[0][row][c8], &Vtb[(size_t)row * Sn + c8]);
    }
    if (tid < 16) cpa16(&s_gl[tid * 4], &ggl[g * Sn + tid * 4]);
    CP_COMMIT();

    float acc2[8][4];
    #pragma unroll
    for (int j = 0; j < 8; j++)
        #pragma unroll
        for (int q = 0; q < 4; q++) acc2[j][q] = 0.f;

    const int trg0 = t0 + w * 16 + lr;
    const int trg1 = trg0 + 8;

    const int nT = 2 * tblk + 2;
    for (int Tb = 0; Tb < nT; Tb++) {
        const int T0 = Tb * 64;
        const int cur = Tb & 1;

        __syncthreads();
        if (Tb + 1 < nT) {
            const int Tn = (Tb + 1) * 64;
            const int nxt = cur ^ 1;
            #pragma unroll
            for (int t = tid; t < 512; t += 256) {
                const int row = t >> 3, c8 = (t & 7) * 8;
                cpa16(&Ks[nxt][row][c8], &Kbase[(size_t)(b * Sn + Tn + row) * QKVW + c8]);
                cpa16(&Vt[nxt][row][c8], &Vtb[(size_t)row * Sn + Tn + c8]);
            }
            if (tid < 16) cpa16(&s_gl[nxt * 64 + tid * 4], &ggl[g * Sn + Tn + tid * 4]);
        }
        CP_COMMIT();
        CP_WAIT(1);
        __syncthreads();

        // stage 1: S = Q . K
        float acc1[8][4];
        #pragma unroll
        for (int j = 0; j < 8; j++)
            #pragma unroll
            for (int q = 0; q < 4; q++) acc1[j][q] = 0.f;

        #pragma unroll
        for (int ks = 0; ks < 4; ks++) {
            const int kb = ks * 16;
            const uint32_t a0 = LDU32(&Qs[w * 16 + lr][kb + 2 * lc]);
            const uint32_t a1 = LDU32(&Qs[w * 16 + 8 + lr][kb + 2 * lc]);
            const uint32_t a2 = LDU32(&Qs[w * 16 + lr][kb + 2 * lc + 8]);
            const uint32_t a3 = LDU32(&Qs[w * 16 + 8 + lr][kb + 2 * lc + 8]);
            #pragma unroll
            for (int jn = 0; jn < 8; jn++) {
                const uint32_t b0 = LDU32(&Ks[cur][jn * 8 + lr][kb + 2 * lc]);
                const uint32_t b1 = LDU32(&Ks[cur][jn * 8 + lr][kb + 2 * lc + 8]);
                mma16(acc1[jn], a0, a1, a2, a3, b0, b1);
            }
        }

        // softmax apply in registers -> packed fp16 P fragments
        const float* smv = &s_gl[cur * 64];
        const bool diag = (Tb >= 2 * tblk);
        uint32_t aP[8][2];
        #pragma unroll
        for (int jn = 0; jn < 8; jn++) {
            const int Tcol = jn * 8 + 2 * lc;
            const int Tg = T0 + Tcol;
            const float2 gl = *(const float2*)&smv[Tcol];
            float p00 = fex2(acc1[jn][0] - gl.x);
            float p01 = fex2(acc1[jn][1] - gl.y);
            float p10 = fex2(acc1[jn][2] - gl.x);
            float p11 = fex2(acc1[jn][3] - gl.y);
            if (diag) {
                if (trg0 < Tg)     p00 = 0.f;
                if (trg0 < Tg + 1) p01 = 0.f;
                if (trg1 < Tg)     p10 = 0.f;
                if (trg1 < Tg + 1) p11 = 0.f;
            }
            aP[jn][0] = pack2h(p00, p01);   // row lr,   k = Tcol, Tcol+1
            aP[jn][1] = pack2h(p10, p11);   // row lr+8
        }

        // stage 2: O += P @ V  (A = packed P fragments; B from transposed V)
        #pragma unroll
        for (int kt = 0; kt < 4; kt++) {
            const uint32_t a0 = aP[2 * kt][0];
            const uint32_t a1 = aP[2 * kt][1];
            const uint32_t a2 = aP[2 * kt + 1][0];
            const uint32_t a3 = aP[2 * kt + 1][1];
            const int kb = kt * 16;
            #pragma unroll
            for (int dn = 0; dn < 8; dn++) {
                const int d = dn * 8 + lr;
                const uint32_t b0 = LDU32(&Vt[cur][d][kb + 2 * lc]);
                const uint32_t b1 = LDU32(&Vt[cur][d][kb + 2 * lc + 8]);
                mma16(acc2[dn], a0, a1, a2, a3, b0, b1);
            }
        }
    }

    #pragma unroll
    for (int dn = 0; dn < 8; dn++) {
        const int col = hq * HDn + dn * 8 + lc * 2;
        *(uint32_t*)&O[(size_t)(b * Sn + trg0) * (HQn * HDn) + col] =
            pack2h(acc2[dn][0], acc2[dn][1]);
        *(uint32_t*)&O[(size_t)(b * Sn + trg1) * (HQn * HDn) + col] =
            pack2h(acc2[dn][2], acc2[dn][3]);
    }
}

// ---------------- launch ----------------
extern "C" void kernel_launch(void* const* d_in, const int* in_sizes, int n_in,
                              void* d_out, int out_size) {
    const float* x    = (const float*)d_in[0];
    const float* ln_g = (const float*)d_in[1];
    const float* ln_b = (const float*)d_in[2];
    const float* Wq   = (const float*)d_in[3];
    const float* bq   = (const float*)d_in[4];
    const float* Wk   = (const float*)d_in[5];
    const float* bk   = (const float*)d_in[6];
    const float* Wv   = (const float*)d_in[7];
    const float* bv   = (const float*)d_in[8];
    const float* Wo   = (const float*)d_in[9];
    const float* bo   = (const float*)d_in[10];
    float* out = (float*)d_out;

    __half *xn, *qkv, *wf, *wo, *attn, *vt;
    float *bf, *gl;
    cudaGetSymbolAddress((void**)&xn,   g_xn);
    cudaGetSymbolAddress((void**)&qkv,  g_qkv);
    cudaGetSymbolAddress((void**)&wf,   g_wf);
    cudaGetSymbolAddress((void**)&bf,   g_bf);
    cudaGetSymbolAddress((void**)&wo,   g_wo);
    cudaGetSymbolAddress((void**)&attn, g_attn);
    cudaGetSymbolAddress((void**)&vt,   g_vt);
    cudaGetSymbolAddress((void**)&gl,   g_gl);

    cudaFuncSetAttribute(gemm_f16<1>, cudaFuncAttributeMaxDynamicSharedMemorySize, GEMM_SMEM);
    cudaFuncSetAttribute(gemm_f16<0>, cudaFuncAttributeMaxDynamicSharedMemorySize, GEMM_SMEM);
    cudaFuncSetAttribute(stats_pass,  cudaFuncAttributeMaxDynamicSharedMemorySize, STATS_SMEM);
    cudaFuncSetAttribute(out_pass,    cudaFuncAttributeMaxDynamicSharedMemorySize, OUT_SMEM);

    fused_pre<<<NB_LN + NB_WQKV + NB_WO + NB_BIAS, 256>>>(
        x, ln_g, ln_b, Wq, Wk, Wv, Wo, bq, bk, bv, xn, wf, wo, bf);

    gemm_f16<1><<<dim3(QKVW / 128, ROWS / 128), 256, GEMM_SMEM>>>(
        xn, wf, bf, qkv, ROWS, QKVW, Dn, QSCALE, 1.0f, 2048);

    vtrans<<<dim3(Sn / 32, 512 / 32, Bn), 256>>>(qkv, vt);

    stats_pass<<<dim3(NTB128, NG), 256, STATS_SMEM>>>(qkv, gl);
    out_pass<<<dim3(NTB128, NG), 256, OUT_SMEM>>>(qkv, vt, gl, attn);

    gemm_f16<0><<<dim3(Dn / 128, ROWS / 128), 256, GEMM_SMEM>>>(
        attn, wo, bo, out, ROWS, Dn, HQn * HDn, 1.0f, 1.0f, 0);
}

// round 15
// speedup vs baseline: 2.0629x; 1.1328x over previous
#include <cuda_runtime.h>
#include <cuda_fp16.h>
#include <cuda_bf16.h>
#include <cstdint>
#include <math.h>

#define Bn 2
#define Sn 2048
#define Dn 2048
#define HQn 32
#define HKVn 8
#define HDn 64
#define ROWS (Bn * Sn)
#define NG   (Bn * HQn)
#define NTB64 (Sn / 64)
#define NTB128 (Sn / 128)
#define QKVW 3072
#define QSCALE 0.18033688011112042f   // 0.125 * log2(e)

// ---------------- scratch ----------------
__device__ __half g_xn[ROWS * Dn];
__device__ __half g_qkv[(size_t)ROWS * QKVW];
__device__ __half g_wf[(size_t)QKVW * Dn];         // transposed [n][k]
__device__ float  g_bf[QKVW];
__device__ __half g_wo[(size_t)Dn * Dn];           // transposed [n][k]
__device__ __half g_attn[ROWS * (HQn * HDn)];
__device__ __half g_vt[(size_t)Bn * 512 * Sn];     // V transposed [b][h*64+d][T]
__device__ float  g_gl[NG * Sn];                   // m + log2(Z)

// ---------------- helpers ----------------
__device__ __forceinline__ float fex2(float x) {
    float r; asm("ex2.approx.ftz.f32 %0, %1;" : "=f"(r) : "f"(x)); return r;
}
__device__ __forceinline__ float flg2(float x) {
    float r; asm("lg2.approx.ftz.f32 %0, %1;" : "=f"(r) : "f"(x)); return r;
}
__device__ __forceinline__ uint32_t pack2h(float x, float y) {
    __half2 h = __floats2half2_rn(x, y);
    return *(uint32_t*)&h;
}
__device__ __forceinline__ void mma16(float* c, uint32_t a0, uint32_t a1, uint32_t a2,
                                      uint32_t a3, uint32_t b0, uint32_t b1) {
    asm volatile(
        "mma.sync.aligned.m16n8k16.row.col.f32.f16.f16.f32 "
        "{%0,%1,%2,%3}, {%4,%5,%6,%7}, {%8,%9}, {%0,%1,%2,%3};"
        : "+f"(c[0]), "+f"(c[1]), "+f"(c[2]), "+f"(c[3])
        : "r"(a0), "r"(a1), "r"(a2), "r"(a3), "r"(b0), "r"(b1));
}
__device__ __forceinline__ void ldsm4(uint32_t* r, uint32_t addr) {
    asm volatile("ldmatrix.sync.aligned.m8n8.x4.shared.b16 {%0,%1,%2,%3}, [%4];"
        : "=r"(r[0]), "=r"(r[1]), "=r"(r[2]), "=r"(r[3]) : "r"(addr));
}
__device__ __forceinline__ uint32_t s2u(const void* p) {
    return (uint32_t)__cvta_generic_to_shared(p);
}
__device__ __forceinline__ void cpa16(void* dst_smem, const void* src) {
    uint32_t d = (uint32_t)__cvta_generic_to_shared(dst_smem);
    asm volatile("cp.async.cg.shared.global [%0], [%1], 16;" :: "r"(d), "l"(src));
}
#define CP_COMMIT() asm volatile("cp.async.commit_group;")
#define CP_WAIT(n)  asm volatile("cp.async.wait_group %0;" :: "n"(n))
#define NEGBIG (-1e30f)

// ---------------- fused pre: LN + weight transpose/convert + bias ----------------
#define NB_LN   ROWS
#define NB_WQKV ((Dn / 32) * (QKVW / 32))
#define NB_WO   ((Dn / 32) * (Dn / 32))
#define NB_BIAS 12
__global__ __launch_bounds__(256) void fused_pre(
    const float* __restrict__ x, const float* __restrict__ gamma,
    const float* __restrict__ beta,
    const float* __restrict__ Wq, const float* __restrict__ Wk,
    const float* __restrict__ Wv, const float* __restrict__ Wo,
    const float* __restrict__ bq, const float* __restrict__ bk,
    const float* __restrict__ bv,
    __half* __restrict__ xn, __half* __restrict__ Wf,
    __half* __restrict__ Wr, float* __restrict__ bf)
{
    __shared__ float red[256];
    __shared__ __half tileh[32][33];
    const int blk = blockIdx.x;
    const int tid = threadIdx.x;

    if (blk < NB_LN) {
        const int row = blk;
        const float* xr = x + (size_t)row * Dn;
        __half* outr = xn + (size_t)row * Dn;

        float s = 0.f;
        for (int c = tid; c < Dn; c += 256) s += xr[c];
        red[tid] = s; __syncthreads();
        for (int off = 128; off > 0; off >>= 1) {
            if (tid < off) red[tid] += red[tid + off];
            __syncthreads();
        }
        const float mu = red[0] * (1.0f / Dn);
        __syncthreads();

        float v = 0.f;
        for (int c = tid; c < Dn; c += 256) { float d = xr[c] - mu; v += d * d; }
        red[tid] = v; __syncthreads();
        for (int off = 128; off > 0; off >>= 1) {
            if (tid < off) red[tid] += red[tid + off];
            __syncthreads();
        }
        const float rstd = rsqrtf(red[0] * (1.0f / Dn) + 1e-5f);
        __syncthreads();

        for (int c = tid; c < Dn; c += 256)
            outr[c] = __float2half((xr[c] - mu) * rstd * gamma[c] + beta[c]);
    } else if (blk < NB_LN + NB_WQKV) {
        const int tidx = blk - NB_LN;
        const int tk = tidx & 63, tn = tidx >> 6;
        const int tx = tid & 31, ty = tid >> 5;
        #pragma unroll
        for (int i = 0; i < 32; i += 8) {
            const int k = tk * 32 + ty + i;
            const int n = tn * 32 + tx;
            float val;
            if (n < 2048)      val = Wq[(size_t)k * 2048 + n];
            else if (n < 2560) val = Wk[(size_t)k * 512 + n - 2048];
            else               val = Wv[(size_t)k * 512 + n - 2560];
            tileh[ty + i][tx] = __float2half(val);
        }
        __syncthreads();
        #pragma unroll
        for (int i = 0; i < 32; i += 8)
            Wf[(size_t)(tn * 32 + ty + i) * Dn + tk * 32 + tx] = tileh[tx][ty + i];
    } else if (blk < NB_LN + NB_WQKV + NB_WO) {
        const int tidx = blk - NB_LN - NB_WQKV;
        const int tk = tidx & 63, tn = tidx >> 6;
        const int tx = tid & 31, ty = tid >> 5;
        #pragma unroll
        for (int i = 0; i < 32; i += 8)
            tileh[ty + i][tx] = __float2half(Wo[(size_t)(tk * 32 + ty + i) * 2048 + tn * 32 + tx]);
        __syncthreads();
        #pragma unroll
        for (int i = 0; i < 32; i += 8)
            Wr[(size_t)(tn * 32 + ty + i) * Dn + tk * 32 + tx] = tileh[tx][ty + i];
    } else {
        const int col = (blk - NB_LN - NB_WQKV - NB_WO) * 256 + tid;
        if (col < QKVW)
            bf[col] = col < 2048 ? bq[col] : (col < 2560 ? bk[col - 2048] : bv[col - 2560]);
    }
}

// ---------------- fp16 GEMM with ldmatrix ----------------
#define GSTAGES 3
#define GEMM_SMEM (GSTAGES * 2 * 128 * 40 * 2)

template<int HALF_OUT>
__global__ __launch_bounds__(256, 2) void gemm_f16(
    const __half* __restrict__ A, const __half* __restrict__ Bt,
    const float* __restrict__ bias, void* __restrict__ Cv,
    int M, int N, int K, float scale0, float scale1, int ncut)
{
    extern __shared__ __half smh[];
    __half (*As)[128][40] = (__half(*)[128][40])smh;
    __half (*Bs)[128][40] = (__half(*)[128][40])(smh + GSTAGES * 128 * 40);

    const int tid = threadIdx.x;
    const int lane = tid & 31, wid = tid >> 5;
    const int warp_m = wid & 3, warp_n = wid >> 2;
    const int m0 = blockIdx.y * 128, n0 = blockIdx.x * 128;
    const int lr = lane >> 2, lc = lane & 3;

    // ldmatrix per-lane offsets (stride 40 halves = 80 bytes)
    const int aoff = (warp_m * 32 + (lane & 15)) * 80 + (lane >> 4) * 16;
    const int boff = (warp_n * 64 + (lane >> 4) * 8 + (lane & 7)) * 80 + ((lane >> 3) & 1) * 16;

    const int KT = K / 32;

    float acc[2][8][4];
    #pragma unroll
    for (int i = 0; i < 2; i++)
        #pragma unroll
        for (int j = 0; j < 8; j++)
            #pragma unroll
            for (int q = 0; q < 4; q++) acc[i][j][q] = 0.f;

    #pragma unroll
    for (int s = 0; s < GSTAGES - 1; s++) {
        const int k0 = s * 32;
        #pragma unroll
        for (int t = tid; t < 512; t += 256) {
            const int row = t >> 2, cg = (t & 3) * 8;
            cpa16(&As[s][row][cg], &A[(size_t)(m0 + row) * K + k0 + cg]);
            cpa16(&Bs[s][row][cg], &Bt[(size_t)(n0 + row) * K + k0 + cg]);
        }
        CP_COMMIT();
    }

    for (int kt = 0; kt < KT; kt++) {
        CP_WAIT(GSTAGES - 2);
        __syncthreads();

        const int nf = kt + GSTAGES - 1;
        if (nf < KT) {
            const int s = nf % GSTAGES;
            const int k0 = nf * 32;
            #pragma unroll
            for (int t = tid; t < 512; t += 256) {
                const int row = t >> 2, cg = (t & 3) * 8;
                cpa16(&As[s][row][cg], &A[(size_t)(m0 + row) * K + k0 + cg]);
                cpa16(&Bs[s][row][cg], &Bt[(size_t)(n0 + row) * K + k0 + cg]);
            }
        }
        CP_COMMIT();

        const int cur = kt % GSTAGES;
        const uint32_t sA = s2u(&As[cur][0][0]);
        const uint32_t sB = s2u(&Bs[cur][0][0]);
        #pragma unroll
        for (int ks = 0; ks < 2; ks++) {
            const int kbb = ks * 32;   // bytes: 16 halves
            uint32_t af[2][4];
            ldsm4(af[0], sA + aoff + kbb);
            ldsm4(af[1], sA + aoff + 16 * 80 + kbb);
            #pragma unroll
            for (int p = 0; p < 4; p++) {
                uint32_t bq[4];
                ldsm4(bq, sB + boff + p * 16 * 80 + kbb);
                #pragma unroll
                for (int im = 0; im < 2; im++) {
                    mma16(acc[im][2 * p],     af[im][0], af[im][1], af[im][2], af[im][3], bq[0], bq[1]);
                    mma16(acc[im][2 * p + 1], af[im][0], af[im][1], af[im][2], af[im][3], bq[2], bq[3]);
                }
            }
        }
    }

    #pragma unroll
    for (int im = 0; im < 2; im++)
        #pragma unroll
        for (int jn = 0; jn < 8; jn++) {
            const int row = m0 + warp_m * 32 + im * 16 + lr;
            const int col = n0 + warp_n * 64 + jn * 8 + lc * 2;
            const float sc = (col < ncut) ? scale0 : scale1;
            const float bb0 = bias[col], bb1 = bias[col + 1];
            const float v00 = sc * (acc[im][jn][0] + bb0);
            const float v01 = sc * (acc[im][jn][1] + bb1);
            const float v10 = sc * (acc[im][jn][2] + bb0);
            const float v11 = sc * (acc[im][jn][3] + bb1);
            if (HALF_OUT) {
                __half* C = (__half*)Cv;
                *(uint32_t*)&C[(size_t)row * N + col] = pack2h(v00, v01);
                *(uint32_t*)&C[(size_t)(row + 8) * N + col] = pack2h(v10, v11);
            } else {
                float* C = (float*)Cv;
                *(float2*)&C[(size_t)row * N + col] = make_float2(v00, v01);
                *(float2*)&C[(size_t)(row + 8) * N + col] = make_float2(v10, v11);
            }
        }
}

// ---------------- V transpose ----------------
__global__ __launch_bounds__(256) void vtrans(
    const __half* __restrict__ QKV, __half* __restrict__ vT)
{
    __shared__ __half tile[32][33];
    const int b = blockIdx.z;
    const int hd0 = blockIdx.y * 32;
    const int t0 = blockIdx.x * 32;
    const int tx = threadIdx.x & 31, ty = threadIdx.x >> 5;

    #pragma unroll
    for (int i = 0; i < 32; i += 8)
        tile[ty + i][tx] = QKV[(size_t)(b * Sn + t0 + ty + i) * QKVW + 2560 + hd0 + tx];
    __syncthreads();
    #pragma unroll
    for (int i = 0; i < 32; i += 8)
        vT[(size_t)(b * 512 + hd0 + ty + i) * Sn + t0 + tx] = tile[tx][ty + i];
}

// ---------------- pass 1: column softmax stats (ldmatrix) ----------------
#define STATS_SMEM ((128 * 72 + 2 * 64 * 72) * 2)
__global__ __launch_bounds__(256, 3) void stats_pass(
    const __half* __restrict__ QKV, float* __restrict__ ggl)
{
    extern __shared__ __half smh[];
    __half (*Ks)[72] = (__half(*)[72])smh;
    __half (*Qs)[64][72] = (__half(*)[64][72])(smh + 128 * 72);

    const int g = blockIdx.y;
    const int b = g >> 5, hq = g & 31, h = hq >> 2;
    const int Tb = blockIdx.x;
    const int T0 = Tb * 128;

    const int tid = threadIdx.x;
    const int lane = tid & 31, w = tid >> 5;
    const int lr = lane >> 2, lc = lane & 3;

    // ldmatrix per-lane offsets (stride 72 halves = 144 bytes)
    const int aoff = (w * 16 + (lane & 15)) * 144 + (lane >> 4) * 16;
    const int boff = ((lane >> 4) * 8 + (lane & 7)) * 144 + ((lane >> 3) & 1) * 16;

    const __half* Kbase = QKV + 2048 + h * HDn;
    const __half* Qbase = QKV + hq * HDn;

    #pragma unroll
    for (int p = 0; p < 4; p++) {
        const int row = p * 32 + (tid >> 3);
        const int c8 = (tid & 7) * 8;
        *(float4*)&Ks[row][c8] =
            *(const float4*)&Kbase[(size_t)(b * Sn + T0 + row) * QKVW + c8];
    }
    const uint32_t sK = s2u(&Ks[0][0]);

    const int tb0 = 2 * Tb;
    #pragma unroll
    for (int t = tid; t < 512; t += 256) {
        const int row = t >> 3, c8 = (t & 7) * 8;
        cpa16(&Qs[0][row][c8], &Qbase[(size_t)(b * Sn + tb0 * 64 + row) * QKVW + c8]);
    }
    CP_COMMIT();

    const int Trow0 = T0 + w * 16 + lr;
    const int Trow1 = Trow0 + 8;

    float m0 = NEGBIG, z0 = 0.f, m1 = NEGBIG, z1 = 0.f;

    for (int tb = tb0; tb < NTB64; tb++) {
        const int cur = (tb - tb0) & 1;
        __syncthreads();
        if (tb + 1 < NTB64) {
            #pragma unroll
            for (int t = tid; t < 512; t += 256) {
                const int row = t >> 3, c8 = (t & 7) * 8;
                cpa16(&Qs[cur ^ 1][row][c8],
                      &Qbase[(size_t)(b * Sn + (tb + 1) * 64 + row) * QKVW + c8]);
            }
        }
        CP_COMMIT();
        CP_WAIT(1);
        __syncthreads();

        float acc[8][4];
        #pragma unroll
        for (int j = 0; j < 8; j++)
            #pragma unroll
            for (int q = 0; q < 4; q++) acc[j][q] = 0.f;

        const uint32_t sQ = s2u(&Qs[cur][0][0]);
        #pragma unroll
        for (int ks = 0; ks < 4; ks++) {
            const int kbb = ks * 32;   // 16 halves in bytes
            uint32_t a[4];
            ldsm4(a, sK + aoff + kbb);
            #pragma unroll
            for (int p = 0; p < 4; p++) {
                uint32_t bq[4];
                ldsm4(bq, sQ + boff + p * 16 * 144 + kbb);
                mma16(acc[2 * p],     a[0], a[1], a[2], a[3], bq[0], bq[1]);
                mma16(acc[2 * p + 1], a[0], a[1], a[2], a[3], bq[2], bq[3]);
            }
        }

        if (tb > tb0 + 1) {
            float tm0 = NEGBIG, tm1 = NEGBIG;
            #pragma unroll
            for (int jn = 0; jn < 8; jn++) {
                tm0 = fmaxf(tm0, fmaxf(acc[jn][0], acc[jn][1]));
                tm1 = fmaxf(tm1, fmaxf(acc[jn][2], acc[jn][3]));
            }
            const float nm0 = fmaxf(m0, tm0);
            const float nm1 = fmaxf(m1, tm1);
            float s0 = 0.f, s1 = 0.f;
            #pragma unroll
            for (int jn = 0; jn < 8; jn++) {
                s0 += fex2(acc[jn][0] - nm0) + fex2(acc[jn][1] - nm0);
                s1 += fex2(acc[jn][2] - nm1) + fex2(acc[jn][3] - nm1);
            }
            z0 = z0 * fex2(m0 - nm0) + s0; m0 = nm0;
            z1 = z1 * fex2(m1 - nm1) + s1; m1 = nm1;
        } else {
            const int tbase = tb * 64 + lc * 2;
            float tm0 = NEGBIG, tm1 = NEGBIG;
            float va[8][4];
            #pragma unroll
            for (int jn = 0; jn < 8; jn++) {
                const int tcol = tbase + jn * 8;
                va[jn][0] = (tcol     >= Trow0) ? acc[jn][0] : NEGBIG;
                va[jn][1] = (tcol + 1 >= Trow0) ? acc[jn][1] : NEGBIG;
                va[jn][2] = (tcol     >= Trow1) ? acc[jn][2] : NEGBIG;
                va[jn][3] = (tcol + 1 >= Trow1) ? acc[jn][3] : NEGBIG;
                tm0 = fmaxf(tm0, fmaxf(va[jn][0], va[jn][1]));
                tm1 = fmaxf(tm1, fmaxf(va[jn][2], va[jn][3]));
            }
            const float nm0 = fmaxf(m0, tm0);
            const float nm1 = fmaxf(m1, tm1);
            float s0 = 0.f, s1 = 0.f;
            #pragma unroll
            for (int jn = 0; jn < 8; jn++) {
                s0 += fex2(va[jn][0] - nm0) + fex2(va[jn][1] - nm0);
                s1 += fex2(va[jn][2] - nm1) + fex2(va[jn][3] - nm1);
            }
            z0 = z0 * fex2(m0 - nm0) + s0; m0 = nm0;
            z1 = z1 * fex2(m1 - nm1) + s1; m1 = nm1;
        }
    }

    #pragma unroll
    for (int off = 1; off < 4; off <<= 1) {
        float mo = __shfl_xor_sync(0xffffffffu, m0, off);
        float zo = __shfl_xor_sync(0xffffffffu, z0, off);
        float mn = fmaxf(m0, mo);
        z0 = z0 * fex2(m0 - mn) + zo * fex2(mo - mn); m0 = mn;
        mo = __shfl_xor_sync(0xffffffffu, m1, off);
        zo = __shfl_xor_sync(0xffffffffu, z1, off);
        mn = fmaxf(m1, mo);
        z1 = z1 * fex2(m1 - mn) + zo * fex2(mo - mn); m1 = mn;
    }
    if (lc == 0) {
        ggl[g * Sn + Trow0] = m0 + flg2(z0);
        ggl[g * Sn + Trow1] = m1 + flg2(z1);
    }
}

// ---------------- pass 2: register-P flash, ldmatrix operands ----------------
#define OUT_SMEM ((128 * 72 + 2 * 64 * 72 + 2 * 64 * 72) * 2 + 2 * 64 * 4)
__global__ __launch_bounds__(256, 2) void out_pass(
    const __half* __restrict__ QKV, const __half* __restrict__ vT,
    const float* __restrict__ ggl, __half* __restrict__ O)
{
    extern __shared__ __half smh[];
    __half (*Qs)[72] = (__half(*)[72])smh;
    __half (*Ks)[64][72] = (__half(*)[64][72])(smh + 128 * 72);
    __half (*Vt)[64][72] = (__half(*)[64][72])(smh + 128 * 72 + 2 * 64 * 72);
    float* s_gl = (float*)(smh + 128 * 72 + 4 * 64 * 72);

    const int g = blockIdx.y;
    const int b = g >> 5, hq = g & 31, h = hq >> 2;
    const int tblk = (NTB128 - 1) - blockIdx.x;
    const int t0 = tblk * 128;

    const int tid = threadIdx.x;
    const int lane = tid & 31, w = tid >> 5;
    const int lr = lane >> 2, lc = lane & 3;

    const int aoff = (w * 16 + (lane & 15)) * 144 + (lane >> 4) * 16;
    const int boff = ((lane >> 4) * 8 + (lane & 7)) * 144 + ((lane >> 3) & 1) * 16;

    const __half* Qbase = QKV + hq * HDn;
    const __half* Kbase = QKV + 2048 + h * HDn;
    const __half* Vtb = vT + (size_t)(b * 512 + h * HDn) * Sn;

    #pragma unroll
    for (int p = 0; p < 4; p++) {
        const int t = p * 256 + tid;
        const int row = t >> 3, c8 = (t & 7) * 8;
        *(float4*)&Qs[row][c8] =
            *(const float4*)&Qbase[(size_t)(b * Sn + t0 + row) * QKVW + c8];
    }
    const uint32_t sQ = s2u(&Qs[0][0]);

    #pragma unroll
    for (int t = tid; t < 512; t += 256) {
        const int row = t >> 3, c8 = (t & 7) * 8;
        cpa16(&Ks[0][row][c8], &Kbase[(size_t)(b * Sn + row) * QKVW + c8]);
        cpa16(&Vt[0][row][c8], &Vtb[(size_t)row * Sn + c8]);
    }
    if (tid < 16) cpa16(&s_gl[tid * 4], &ggl[g * Sn + tid * 4]);
    CP_COMMIT();

    float acc2[8][4];
    #pragma unroll
    for (int j = 0; j < 8; j++)
        #pragma unroll
        for (int q = 0; q < 4; q++) acc2[j][q] = 0.f;

    const int trg0 = t0 + w * 16 + lr;
    const int trg1 = trg0 + 8;

    const int nT = 2 * tblk + 2;
    for (int Tb = 0; Tb < nT; Tb++) {
        const int T0 = Tb * 64;
        const int cur = Tb & 1;

        __syncthreads();
        if (Tb + 1 < nT) {
            const int Tn = (Tb + 1) * 64;
            const int nxt = cur ^ 1;
            #pragma unroll
            for (int t = tid; t < 512; t += 256) {
                const int row = t >> 3, c8 = (t & 7) * 8;
                cpa16(&Ks[nxt][row][c8], &Kbase[(size_t)(b * Sn + Tn + row) * QKVW + c8]);
                cpa16(&Vt[nxt][row][c8], &Vtb[(size_t)row * Sn + Tn + c8]);
            }
            if (tid < 16) cpa16(&s_gl[nxt * 64 + tid * 4], &ggl[g * Sn + Tn + tid * 4]);
        }
        CP_COMMIT();
        CP_WAIT(1);
        __syncthreads();

        // stage 1: S = Q . K
        float acc1[8][4];
        #pragma unroll
        for (int j = 0; j < 8; j++)
            #pragma unroll
            for (int q = 0; q < 4; q++) acc1[j][q] = 0.f;

        const uint32_t sK = s2u(&Ks[cur][0][0]);
        #pragma unroll
        for (int ks = 0; ks < 4; ks++) {
            const int kbb = ks * 32;
            uint32_t a[4];
            ldsm4(a, sQ + aoff + kbb);
            #pragma unroll
            for (int p = 0; p < 4; p++) {
                uint32_t bq[4];
                ldsm4(bq, sK + boff + p * 16 * 144 + kbb);
                mma16(acc1[2 * p],     a[0], a[1], a[2], a[3], bq[0], bq[1]);
                mma16(acc1[2 * p + 1], a[0], a[1], a[2], a[3], bq[2], bq[3]);
            }
        }

        // softmax apply in registers -> packed fp16 P fragments
        const float* smv = &s_gl[cur * 64];
        const bool diag = (Tb >= 2 * tblk);
        uint32_t aP[8][2];
        #pragma unroll
        for (int jn = 0; jn < 8; jn++) {
            const int Tcol = jn * 8 + 2 * lc;
            const int Tg = T0 + Tcol;
            const float2 gl = *(const float2*)&smv[Tcol];
            float p00 = fex2(acc1[jn][0] - gl.x);
            float p01 = fex2(acc1[jn][1] - gl.y);
            float p10 = fex2(acc1[jn][2] - gl.x);
            float p11 = fex2(acc1[jn][3] - gl.y);
            if (diag) {
                if (trg0 < Tg)     p00 = 0.f;
                if (trg0 < Tg + 1) p01 = 0.f;
                if (trg1 < Tg)     p10 = 0.f;
                if (trg1 < Tg + 1) p11 = 0.f;
            }
            aP[jn][0] = pack2h(p00, p01);
            aP[jn][1] = pack2h(p10, p11);
        }

        // stage 2: O += P @ V
        const uint32_t sV = s2u(&Vt[cur][0][0]);
        #pragma unroll
        for (int kt = 0; kt < 4; kt++) {
            const uint32_t a0 = aP[2 * kt][0];
            const uint32_t a1 = aP[2 * kt][1];
            const uint32_t a2 = aP[2 * kt + 1][0];
            const uint32_t a3 = aP[2 * kt + 1][1];
            const int kbb = kt * 32;
            #pragma unroll
            for (int p = 0; p < 4; p++) {
                uint32_t bv4[4];
                ldsm4(bv4, sV + boff + p * 16 * 144 + kbb);
                mma16(acc2[2 * p],     a0, a1, a2, a3, bv4[0], bv4[1]);
                mma16(acc2[2 * p + 1], a0, a1, a2, a3, bv4[2], bv4[3]);
            }
        }
    }

    #pragma unroll
    for (int dn = 0; dn < 8; dn++) {
        const int col = hq * HDn + dn * 8 + lc * 2;
        *(uint32_t*)&O[(size_t)(b * Sn + trg0) * (HQn * HDn) + col] =
            pack2h(acc2[dn][0], acc2[dn][1]);
        *(uint32_t*)&O[(size_t)(b * Sn + trg1) * (HQn * HDn) + col] =
            pack2h(acc2[dn][2], acc2[dn][3]);
    }
}

// ---------------- launch ----------------
extern "C" void kernel_launch(void* const* d_in, const int* in_sizes, int n_in,
                              void* d_out, int out_size) {
    const float* x    = (const float*)d_in[0];
    const float* ln_g = (const float*)d_in[1];
    const float* ln_b = (const float*)d_in[2];
    const float* Wq   = (const float*)d_in[3];
    const float* bq   = (const float*)d_in[4];
    const float* Wk   = (const float*)d_in[5];
    const float* bk   = (const float*)d_in[6];
    const float* Wv   = (const float*)d_in[7];
    const float* bv   = (const float*)d_in[8];
    const float* Wo   = (const float*)d_in[9];
    const float* bo   = (const float*)d_in[10];
    float* out = (float*)d_out;

    __half *xn, *qkv, *wf, *wo, *attn, *vt;
    float *bf, *gl;
    cudaGetSymbolAddress((void**)&xn,   g_xn);
    cudaGetSymbolAddress((void**)&qkv,  g_qkv);
    cudaGetSymbolAddress((void**)&wf,   g_wf);
    cudaGetSymbolAddress((void**)&bf,   g_bf);
    cudaGetSymbolAddress((void**)&wo,   g_wo);
    cudaGetSymbolAddress((void**)&attn, g_attn);
    cudaGetSymbolAddress((void**)&vt,   g_vt);
    cudaGetSymbolAddress((void**)&gl,   g_gl);

    cudaFuncSetAttribute(gemm_f16<1>, cudaFuncAttributeMaxDynamicSharedMemorySize, GEMM_SMEM);
    cudaFuncSetAttribute(gemm_f16<0>, cudaFuncAttributeMaxDynamicSharedMemorySize, GEMM_SMEM);
    cudaFuncSetAttribute(stats_pass,  cudaFuncAttributeMaxDynamicSharedMemorySize, STATS_SMEM);
    cudaFuncSetAttribute(out_pass,    cudaFuncAttributeMaxDynamicSharedMemorySize, OUT_SMEM);

    fused_pre<<<NB_LN + NB_WQKV + NB_WO + NB_BIAS, 256>>>(
        x, ln_g, ln_b, Wq, Wk, Wv, Wo, bq, bk, bv, xn, wf, wo, bf);

    gemm_f16<1><<<dim3(QKVW / 128, ROWS / 128), 256, GEMM_SMEM>>>(
        xn, wf, bf, qkv, ROWS, QKVW, Dn, QSCALE, 1.0f, 2048);

    vtrans<<<dim3(Sn / 32, 512 / 32, Bn), 256>>>(qkv, vt);

    stats_pass<<<dim3(NTB128, NG), 256, STATS_SMEM>>>(qkv, gl);
    out_pass<<<dim3(NTB128, NG), 256, OUT_SMEM>>>(qkv, vt, gl, attn);

    gemm_f16<0><<<dim3(Dn / 128, ROWS / 128), 256, GEMM_SMEM>>>(
        attn, wo, bo, out, ROWS, Dn, HQn * HDn, 1.0f, 1.0f, 0);
}

// round 16
// speedup vs baseline: 2.0960x; 1.0161x over previous
#include <cuda_runtime.h>
#include <cuda_fp16.h>
#include <cuda_bf16.h>
#include <cstdint>
#include <math.h>

#define Bn 2
#define Sn 2048
#define Dn 2048
#define HQn 32
#define HKVn 8
#define HDn 64
#define ROWS (Bn * Sn)
#define NG   (Bn * HQn)
#define NTB64 (Sn / 64)
#define NTB128 (Sn / 128)
#define QKVW 3072
#define QSCALE 0.18033688011112042f   // 0.125 * log2(e)

// ---------------- scratch ----------------
__device__ __half g_xn[ROWS * Dn];
__device__ __half g_qkv[(size_t)ROWS * QKVW];
__device__ __half g_wf[(size_t)QKVW * Dn];         // transposed [n][k]
__device__ float  g_bf[QKVW];
__device__ __half g_wo[(size_t)Dn * Dn];           // transposed [n][k]
__device__ __half g_attn[ROWS * (HQn * HDn)];
__device__ __half g_vt[(size_t)Bn * 512 * Sn];     // V transposed [b][h*64+d][T]
__device__ float  g_gl[NG * Sn];                   // m + log2(Z)

// ---------------- helpers ----------------
__device__ __forceinline__ float fex2(float x) {
    float r; asm("ex2.approx.ftz.f32 %0, %1;" : "=f"(r) : "f"(x)); return r;
}
__device__ __forceinline__ float flg2(float x) {
    float r; asm("lg2.approx.ftz.f32 %0, %1;" : "=f"(r) : "f"(x)); return r;
}
__device__ __forceinline__ uint32_t pack2h(float x, float y) {
    __half2 h = __floats2half2_rn(x, y);
    return *(uint32_t*)&h;
}
__device__ __forceinline__ uint32_t h2ex2(uint32_t a) {   // exp2 on packed half2
    uint32_t r; asm("ex2.approx.f16x2 %0, %1;" : "=r"(r) : "r"(a)); return r;
}
__device__ __forceinline__ float2 h2tof2(uint32_t a) {
    __half2 h = *(__half2*)&a;
    return __half22float2(h);
}
__device__ __forceinline__ void mma16(float* c, uint32_t a0, uint32_t a1, uint32_t a2,
                                      uint32_t a3, uint32_t b0, uint32_t b1) {
    asm volatile(
        "mma.sync.aligned.m16n8k16.row.col.f32.f16.f16.f32 "
        "{%0,%1,%2,%3}, {%4,%5,%6,%7}, {%8,%9}, {%0,%1,%2,%3};"
        : "+f"(c[0]), "+f"(c[1]), "+f"(c[2]), "+f"(c[3])
        : "r"(a0), "r"(a1), "r"(a2), "r"(a3), "r"(b0), "r"(b1));
}
__device__ __forceinline__ void ldsm4(uint32_t* r, uint32_t addr) {
    asm volatile("ldmatrix.sync.aligned.m8n8.x4.shared.b16 {%0,%1,%2,%3}, [%4];"
        : "=r"(r[0]), "=r"(r[1]), "=r"(r[2]), "=r"(r[3]) : "r"(addr));
}
__device__ __forceinline__ uint32_t s2u(const void* p) {
    return (uint32_t)__cvta_generic_to_shared(p);
}
__device__ __forceinline__ void cpa16(void* dst_smem, const void* src) {
    uint32_t d = (uint32_t)__cvta_generic_to_shared(dst_smem);
    asm volatile("cp.async.cg.shared.global [%0], [%1], 16;" :: "r"(d), "l"(src));
}
#define CP_COMMIT() asm volatile("cp.async.commit_group;")
#define CP_WAIT(n)  asm volatile("cp.async.wait_group %0;" :: "n"(n))
#define NEGBIG (-1e30f)

// ---------------- fused pre: single-pass LN + weight transpose/convert + bias ----------------
#define NB_LN   ROWS
#define NB_WQKV ((Dn / 32) * (QKVW / 32))
#define NB_WO   ((Dn / 32) * (Dn / 32))
#define NB_BIAS 12
__global__ __launch_bounds__(256) void fused_pre(
    const float* __restrict__ x, const float* __restrict__ gamma,
    const float* __restrict__ beta,
    const float* __restrict__ Wq, const float* __restrict__ Wk,
    const float* __restrict__ Wv, const float* __restrict__ Wo,
    const float* __restrict__ bq, const float* __restrict__ bk,
    const float* __restrict__ bv,
    __half* __restrict__ xn, __half* __restrict__ Wf,
    __half* __restrict__ Wr, float* __restrict__ bf)
{
    __shared__ float red[256];
    __shared__ float red2[256];
    __shared__ __half tileh[32][33];
    const int blk = blockIdx.x;
    const int tid = threadIdx.x;

    if (blk < NB_LN) {
        const int row = blk;
        const float* xr = x + (size_t)row * Dn;
        __half* outr = xn + (size_t)row * Dn;
        const int base = tid * 8;

        const float4 v0 = *(const float4*)&xr[base];
        const float4 v1 = *(const float4*)&xr[base + 4];
        float s  = v0.x + v0.y + v0.z + v0.w + v1.x + v1.y + v1.z + v1.w;
        float s2 = v0.x * v0.x + v0.y * v0.y + v0.z * v0.z + v0.w * v0.w
                 + v1.x * v1.x + v1.y * v1.y + v1.z * v1.z + v1.w * v1.w;
        red[tid] = s; red2[tid] = s2; __syncthreads();
        for (int off = 128; off > 0; off >>= 1) {
            if (tid < off) { red[tid] += red[tid + off]; red2[tid] += red2[tid + off]; }
            __syncthreads();
        }
        const float mu = red[0] * (1.0f / Dn);
        const float var = red2[0] * (1.0f / Dn) - mu * mu;
        const float rstd = rsqrtf(var + 1e-5f);

        const float4 g0 = *(const float4*)&gamma[base];
        const float4 g1 = *(const float4*)&gamma[base + 4];
        const float4 b0 = *(const float4*)&beta[base];
        const float4 b1 = *(const float4*)&beta[base + 4];
        uint4 o;
        o.x = pack2h((v0.x - mu) * rstd * g0.x + b0.x, (v0.y - mu) * rstd * g0.y + b0.y);
        o.y = pack2h((v0.z - mu) * rstd * g0.z + b0.z, (v0.w - mu) * rstd * g0.w + b0.w);
        o.z = pack2h((v1.x - mu) * rstd * g1.x + b1.x, (v1.y - mu) * rstd * g1.y + b1.y);
        o.w = pack2h((v1.z - mu) * rstd * g1.z + b1.z, (v1.w - mu) * rstd * g1.w + b1.w);
        *(uint4*)&outr[base] = o;
    } else if (blk < NB_LN + NB_WQKV) {
        const int tidx = blk - NB_LN;
        const int tk = tidx & 63, tn = tidx >> 6;
        const int tx = tid & 31, ty = tid >> 5;
        #pragma unroll
        for (int i = 0; i < 32; i += 8) {
            const int k = tk * 32 + ty + i;
            const int n = tn * 32 + tx;
            float val;
            if (n < 2048)      val = Wq[(size_t)k * 2048 + n];
            else if (n < 2560) val = Wk[(size_t)k * 512 + n - 2048];
            else               val = Wv[(size_t)k * 512 + n - 2560];
            tileh[ty + i][tx] = __float2half(val);
        }
        __syncthreads();
        #pragma unroll
        for (int i = 0; i < 32; i += 8)
            Wf[(size_t)(tn * 32 + ty + i) * Dn + tk * 32 + tx] = tileh[tx][ty + i];
    } else if (blk < NB_LN + NB_WQKV + NB_WO) {
        const int tidx = blk - NB_LN - NB_WQKV;
        const int tk = tidx & 63, tn = tidx >> 6;
        const int tx = tid & 31, ty = tid >> 5;
        #pragma unroll
        for (int i = 0; i < 32; i += 8)
            tileh[ty + i][tx] = __float2half(Wo[(size_t)(tk * 32 + ty + i) * 2048 + tn * 32 + tx]);
        __syncthreads();
        #pragma unroll
        for (int i = 0; i < 32; i += 8)
            Wr[(size_t)(tn * 32 + ty + i) * Dn + tk * 32 + tx] = tileh[tx][ty + i];
    } else {
        const int col = (blk - NB_LN - NB_WQKV - NB_WO) * 256 + tid;
        if (col < QKVW)
            bf[col] = col < 2048 ? bq[col] : (col < 2560 ? bk[col - 2048] : bv[col - 2560]);
    }
}

// ---------------- fp16 GEMM with ldmatrix, 4-stage cp.async ----------------
#define GSTAGES 4
#define GEMM_SMEM (GSTAGES * 2 * 128 * 40 * 2)

template<int HALF_OUT>
__global__ __launch_bounds__(256, 2) void gemm_f16(
    const __half* __restrict__ A, const __half* __restrict__ Bt,
    const float* __restrict__ bias, void* __restrict__ Cv,
    int M, int N, int K, float scale0, float scale1, int ncut)
{
    extern __shared__ __half smh[];
    __half (*As)[128][40] = (__half(*)[128][40])smh;
    __half (*Bs)[128][40] = (__half(*)[128][40])(smh + GSTAGES * 128 * 40);

    const int tid = threadIdx.x;
    const int lane = tid & 31, wid = tid >> 5;
    const int warp_m = wid & 3, warp_n = wid >> 2;
    const int m0 = blockIdx.y * 128, n0 = blockIdx.x * 128;
    const int lr = lane >> 2, lc = lane & 3;

    const int aoff = (warp_m * 32 + (lane & 15)) * 80 + (lane >> 4) * 16;
    const int boff = (warp_n * 64 + (lane >> 4) * 8 + (lane & 7)) * 80 + ((lane >> 3) & 1) * 16;

    const int KT = K / 32;

    float acc[2][8][4];
    #pragma unroll
    for (int i = 0; i < 2; i++)
        #pragma unroll
        for (int j = 0; j < 8; j++)
            #pragma unroll
            for (int q = 0; q < 4; q++) acc[i][j][q] = 0.f;

    #pragma unroll
    for (int s = 0; s < GSTAGES - 1; s++) {
        const int k0 = s * 32;
        #pragma unroll
        for (int t = tid; t < 512; t += 256) {
            const int row = t >> 2, cg = (t & 3) * 8;
            cpa16(&As[s][row][cg], &A[(size_t)(m0 + row) * K + k0 + cg]);
            cpa16(&Bs[s][row][cg], &Bt[(size_t)(n0 + row) * K + k0 + cg]);
        }
        CP_COMMIT();
    }

    for (int kt = 0; kt < KT; kt++) {
        CP_WAIT(GSTAGES - 2);
        __syncthreads();

        const int nf = kt + GSTAGES - 1;
        if (nf < KT) {
            const int s = nf % GSTAGES;
            const int k0 = nf * 32;
            #pragma unroll
            for (int t = tid; t < 512; t += 256) {
                const int row = t >> 2, cg = (t & 3) * 8;
                cpa16(&As[s][row][cg], &A[(size_t)(m0 + row) * K + k0 + cg]);
                cpa16(&Bs[s][row][cg], &Bt[(size_t)(n0 + row) * K + k0 + cg]);
            }
        }
        CP_COMMIT();

        const int cur = kt % GSTAGES;
        const uint32_t sA = s2u(&As[cur][0][0]);
        const uint32_t sB = s2u(&Bs[cur][0][0]);
        #pragma unroll
        for (int ks = 0; ks < 2; ks++) {
            const int kbb = ks * 32;
            uint32_t af[2][4];
            ldsm4(af[0], sA + aoff + kbb);
            ldsm4(af[1], sA + aoff + 16 * 80 + kbb);
            #pragma unroll
            for (int p = 0; p < 4; p++) {
                uint32_t bq[4];
                ldsm4(bq, sB + boff + p * 16 * 80 + kbb);
                #pragma unroll
                for (int im = 0; im < 2; im++) {
                    mma16(acc[im][2 * p],     af[im][0], af[im][1], af[im][2], af[im][3], bq[0], bq[1]);
                    mma16(acc[im][2 * p + 1], af[im][0], af[im][1], af[im][2], af[im][3], bq[2], bq[3]);
                }
            }
        }
    }

    #pragma unroll
    for (int im = 0; im < 2; im++)
        #pragma unroll
        for (int jn = 0; jn < 8; jn++) {
            const int row = m0 + warp_m * 32 + im * 16 + lr;
            const int col = n0 + warp_n * 64 + jn * 8 + lc * 2;
            const float sc = (col < ncut) ? scale0 : scale1;
            const float bb0 = bias[col], bb1 = bias[col + 1];
            const float v00 = sc * (acc[im][jn][0] + bb0);
            const float v01 = sc * (acc[im][jn][1] + bb1);
            const float v10 = sc * (acc[im][jn][2] + bb0);
            const float v11 = sc * (acc[im][jn][3] + bb1);
            if (HALF_OUT) {
                __half* C = (__half*)Cv;
                *(uint32_t*)&C[(size_t)row * N + col] = pack2h(v00, v01);
                *(uint32_t*)&C[(size_t)(row + 8) * N + col] = pack2h(v10, v11);
            } else {
                float* C = (float*)Cv;
                *(float2*)&C[(size_t)row * N + col] = make_float2(v00, v01);
                *(float2*)&C[(size_t)(row + 8) * N + col] = make_float2(v10, v11);
            }
        }
}

// ---------------- V transpose ----------------
__global__ __launch_bounds__(256) void vtrans(
    const __half* __restrict__ QKV, __half* __restrict__ vT)
{
    __shared__ __half tile[32][33];
    const int b = blockIdx.z;
    const int hd0 = blockIdx.y * 32;
    const int t0 = blockIdx.x * 32;
    const int tx = threadIdx.x & 31, ty = threadIdx.x >> 5;

    #pragma unroll
    for (int i = 0; i < 32; i += 8)
        tile[ty + i][tx] = QKV[(size_t)(b * Sn + t0 + ty + i) * QKVW + 2560 + hd0 + tx];
    __syncthreads();
    #pragma unroll
    for (int i = 0; i < 32; i += 8)
        vT[(size_t)(b * 512 + hd0 + ty + i) * Sn + t0 + tx] = tile[tx][ty + i];
}

// ---------------- pass 1: column softmax stats (ldmatrix + f16x2 exp) ----------------
#define STATS_SMEM ((128 * 72 + 2 * 64 * 72) * 2)
__global__ __launch_bounds__(256, 3) void stats_pass(
    const __half* __restrict__ QKV, float* __restrict__ ggl)
{
    extern __shared__ __half smh[];
    __half (*Ks)[72] = (__half(*)[72])smh;
    __half (*Qs)[64][72] = (__half(*)[64][72])(smh + 128 * 72);

    const int g = blockIdx.y;
    const int b = g >> 5, hq = g & 31, h = hq >> 2;
    const int Tb = blockIdx.x;
    const int T0 = Tb * 128;

    const int tid = threadIdx.x;
    const int lane = tid & 31, w = tid >> 5;
    const int lr = lane >> 2, lc = lane & 3;

    const int aoff = (w * 16 + (lane & 15)) * 144 + (lane >> 4) * 16;
    const int boff = ((lane >> 4) * 8 + (lane & 7)) * 144 + ((lane >> 3) & 1) * 16;

    const __half* Kbase = QKV + 2048 + h * HDn;
    const __half* Qbase = QKV + hq * HDn;

    #pragma unroll
    for (int p = 0; p < 4; p++) {
        const int row = p * 32 + (tid >> 3);
        const int c8 = (tid & 7) * 8;
        *(float4*)&Ks[row][c8] =
            *(const float4*)&Kbase[(size_t)(b * Sn + T0 + row) * QKVW + c8];
    }
    const uint32_t sK = s2u(&Ks[0][0]);

    const int tb0 = 2 * Tb;
    #pragma unroll
    for (int t = tid; t < 512; t += 256) {
        const int row = t >> 3, c8 = (t & 7) * 8;
        cpa16(&Qs[0][row][c8], &Qbase[(size_t)(b * Sn + tb0 * 64 + row) * QKVW + c8]);
    }
    CP_COMMIT();

    const int Trow0 = T0 + w * 16 + lr;
    const int Trow1 = Trow0 + 8;

    float m0 = NEGBIG, z0 = 0.f, m1 = NEGBIG, z1 = 0.f;

    for (int tb = tb0; tb < NTB64; tb++) {
        const int cur = (tb - tb0) & 1;
        __syncthreads();
        if (tb + 1 < NTB64) {
            #pragma unroll
            for (int t = tid; t < 512; t += 256) {
                const int row = t >> 3, c8 = (t & 7) * 8;
                cpa16(&Qs[cur ^ 1][row][c8],
                      &Qbase[(size_t)(b * Sn + (tb + 1) * 64 + row) * QKVW + c8]);
            }
        }
        CP_COMMIT();
        CP_WAIT(1);
        __syncthreads();

        float acc[8][4];
        #pragma unroll
        for (int j = 0; j < 8; j++)
            #pragma unroll
            for (int q = 0; q < 4; q++) acc[j][q] = 0.f;

        const uint32_t sQ = s2u(&Qs[cur][0][0]);
        #pragma unroll
        for (int ks = 0; ks < 4; ks++) {
            const int kbb = ks * 32;
            uint32_t a[4];
            ldsm4(a, sK + aoff + kbb);
            #pragma unroll
            for (int p = 0; p < 4; p++) {
                uint32_t bq[4];
                ldsm4(bq, sQ + boff + p * 16 * 144 + kbb);
                mma16(acc[2 * p],     a[0], a[1], a[2], a[3], bq[0], bq[1]);
                mma16(acc[2 * p + 1], a[0], a[1], a[2], a[3], bq[2], bq[3]);
            }
        }

        // masking (first 2 tiles only)
        if (tb <= tb0 + 1) {
            const int tbase = tb * 64 + lc * 2;
            #pragma unroll
            for (int jn = 0; jn < 8; jn++) {
                const int tcol = tbase + jn * 8;
                if (tcol     < Trow0) acc[jn][0] = NEGBIG;
                if (tcol + 1 < Trow0) acc[jn][1] = NEGBIG;
                if (tcol     < Trow1) acc[jn][2] = NEGBIG;
                if (tcol + 1 < Trow1) acc[jn][3] = NEGBIG;
            }
        }

        float tm0 = NEGBIG, tm1 = NEGBIG;
        #pragma unroll
        for (int jn = 0; jn < 8; jn++) {
            tm0 = fmaxf(tm0, fmaxf(acc[jn][0], acc[jn][1]));
            tm1 = fmaxf(tm1, fmaxf(acc[jn][2], acc[jn][3]));
        }
        const float nm0 = fmaxf(m0, tm0);
        const float nm1 = fmaxf(m1, tm1);
        float s0 = 0.f, s1 = 0.f;
        #pragma unroll
        for (int jn = 0; jn < 8; jn++) {
            const float2 e0 = h2tof2(h2ex2(pack2h(acc[jn][0] - nm0, acc[jn][1] - nm0)));
            const float2 e1 = h2tof2(h2ex2(pack2h(acc[jn][2] - nm1, acc[jn][3] - nm1)));
            s0 += e0.x + e0.y;
            s1 += e1.x + e1.y;
        }
        z0 = z0 * fex2(m0 - nm0) + s0; m0 = nm0;
        z1 = z1 * fex2(m1 - nm1) + s1; m1 = nm1;
    }

    #pragma unroll
    for (int off = 1; off < 4; off <<= 1) {
        float mo = __shfl_xor_sync(0xffffffffu, m0, off);
        float zo = __shfl_xor_sync(0xffffffffu, z0, off);
        float mn = fmaxf(m0, mo);
        z0 = z0 * fex2(m0 - mn) + zo * fex2(mo - mn); m0 = mn;
        mo = __shfl_xor_sync(0xffffffffu, m1, off);
        zo = __shfl_xor_sync(0xffffffffu, z1, off);
        mn = fmaxf(m1, mo);
        z1 = z1 * fex2(m1 - mn) + zo * fex2(mo - mn); m1 = mn;
    }
    if (lc == 0) {
        ggl[g * Sn + Trow0] = m0 + flg2(z0);
        ggl[g * Sn + Trow1] = m1 + flg2(z1);
    }
}

// ---------------- pass 2: register-P flash, f16x2 exp epilogue ----------------
#define OUT_SMEM ((128 * 72 + 2 * 64 * 72 + 2 * 64 * 72) * 2 + 2 * 64 * 4)
__global__ __launch_bounds__(256, 2) void out_pass(
    const __half* __restrict__ QKV, const __half* __restrict__ vT,
    const float* __restrict__ ggl, __half* __restrict__ O)
{
    extern __shared__ __half smh[];
    __half (*Qs)[72] = (__half(*)[72])smh;
    __half (*Ks)[64][72] = (__half(*)[64][72])(smh + 128 * 72);
    __half (*Vt)[64][72] = (__half(*)[64][72])(smh + 128 * 72 + 2 * 64 * 72);
    float* s_gl = (float*)(smh + 128 * 72 + 4 * 64 * 72);

    const int g = blockIdx.y;
    const int b = g >> 5, hq = g & 31, h = hq >> 2;
    const int tblk = (NTB128 - 1) - blockIdx.x;
    const int t0 = tblk * 128;

    const int tid = threadIdx.x;
    const int lane = tid & 31, w = tid >> 5;
    const int lr = lane >> 2, lc = lane & 3;

    const int aoff = (w * 16 + (lane & 15)) * 144 + (lane >> 4) * 16;
    const int boff = ((lane >> 4) * 8 + (lane & 7)) * 144 + ((lane >> 3) & 1) * 16;

    const __half* Qbase = QKV + hq * HDn;
    const __half* Kbase = QKV + 2048 + h * HDn;
    const __half* Vtb = vT + (size_t)(b * 512 + h * HDn) * Sn;

    #pragma unroll
    for (int p = 0; p < 4; p++) {
        const int t = p * 256 + tid;
        const int row = t >> 3, c8 = (t & 7) * 8;
        *(float4*)&Qs[row][c8] =
            *(const float4*)&Qbase[(size_t)(b * Sn + t0 + row) * QKVW + c8];
    }
    const uint32_t sQ = s2u(&Qs[0][0]);

    #pragma unroll
    for (int t = tid; t < 512; t += 256) {
        const int row = t >> 3, c8 = (t & 7) * 8;
        cpa16(&Ks[0][row][c8], &Kbase[(size_t)(b * Sn + row) * QKVW + c8]);
        cpa16(&Vt[0][row][c8], &Vtb[(size_t)row * Sn + c8]);
    }
    if (tid < 16) cpa16(&s_gl[tid * 4], &ggl[g * Sn + tid * 4]);
    CP_COMMIT();

    float acc2[8][4];
    #pragma unroll
    for (int j = 0; j < 8; j++)
        #pragma unroll
        for (int q = 0; q < 4; q++) acc2[j][q] = 0.f;

    const int trg0 = t0 + w * 16 + lr;
    const int trg1 = trg0 + 8;

    const int nT = 2 * tblk + 2;
    for (int Tb = 0; Tb < nT; Tb++) {
        const int T0 = Tb * 64;
        const int cur = Tb & 1;

        __syncthreads();
        if (Tb + 1 < nT) {
            const int Tn = (Tb + 1) * 64;
            const int nxt = cur ^ 1;
            #pragma unroll
            for (int t = tid; t < 512; t += 256) {
                const int row = t >> 3, c8 = (t & 7) * 8;
                cpa16(&Ks[nxt][row][c8], &Kbase[(size_t)(b * Sn + Tn + row) * QKVW + c8]);
                cpa16(&Vt[nxt][row][c8], &Vtb[(size_t)row * Sn + Tn + c8]);
            }
            if (tid < 16) cpa16(&s_gl[nxt * 64 + tid * 4], &ggl[g * Sn + Tn + tid * 4]);
        }
        CP_COMMIT();
        CP_WAIT(1);
        __syncthreads();

        // stage 1: S = Q . K
        float acc1[8][4];
        #pragma unroll
        for (int j = 0; j < 8; j++)
            #pragma unroll
            for (int q = 0; q < 4; q++) acc1[j][q] = 0.f;

        const uint32_t sK = s2u(&Ks[cur][0][0]);
        #pragma unroll
        for (int ks = 0; ks < 4; ks++) {
            const int kbb = ks * 32;
            uint32_t a[4];
            ldsm4(a, sQ + aoff + kbb);
            #pragma unroll
            for (int p = 0; p < 4; p++) {
                uint32_t bq[4];
                ldsm4(bq, sK + boff + p * 16 * 144 + kbb);
                mma16(acc1[2 * p],     a[0], a[1], a[2], a[3], bq[0], bq[1]);
                mma16(acc1[2 * p + 1], a[0], a[1], a[2], a[3], bq[2], bq[3]);
            }
        }

        // softmax apply: pack (s - gl) to half2, one f16x2 exp -> ready fragments
        const float* smv = &s_gl[cur * 64];
        const bool diag = (Tb >= 2 * tblk);
        uint32_t aP[8][2];
        #pragma unroll
        for (int jn = 0; jn < 8; jn++) {
            const int Tcol = jn * 8 + 2 * lc;
            const int Tg = T0 + Tcol;
            const float2 gl = *(const float2*)&smv[Tcol];
            float s00 = acc1[jn][0] - gl.x;
            float s01 = acc1[jn][1] - gl.y;
            float s10 = acc1[jn][2] - gl.x;
            float s11 = acc1[jn][3] - gl.y;
            if (diag) {
                if (trg0 < Tg)     s00 = NEGBIG;
                if (trg0 < Tg + 1) s01 = NEGBIG;
                if (trg1 < Tg)     s10 = NEGBIG;
                if (trg1 < Tg + 1) s11 = NEGBIG;
            }
            aP[jn][0] = h2ex2(pack2h(s00, s01));
            aP[jn][1] = h2ex2(pack2h(s10, s11));
        }

        // stage 2: O += P @ V
        const uint32_t sV = s2u(&Vt[cur][0][0]);
        #pragma unroll
        for (int kt = 0; kt < 4; kt++) {
            const uint32_t a0 = aP[2 * kt][0];
            const uint32_t a1 = aP[2 * kt][1];
            const uint32_t a2 = aP[2 * kt + 1][0];
            const uint32_t a3 = aP[2 * kt + 1][1];
            const int kbb = kt * 32;
            #pragma unroll
            for (int p = 0; p < 4; p++) {
                uint32_t bv4[4];
                ldsm4(bv4, sV + boff + p * 16 * 144 + kbb);
                mma16(acc2[2 * p],     a0, a1, a2, a3, bv4[0], bv4[1]);
                mma16(acc2[2 * p + 1], a0, a1, a2, a3, bv4[2], bv4[3]);
            }
        }
    }

    #pragma unroll
    for (int dn = 0; dn < 8; dn++) {
        const int col = hq * HDn + dn * 8 + lc * 2;
        *(uint32_t*)&O[(size_t)(b * Sn + trg0) * (HQn * HDn) + col] =
            pack2h(acc2[dn][0], acc2[dn][1]);
        *(uint32_t*)&O[(size_t)(b * Sn + trg1) * (HQn * HDn) + col] =
            pack2h(acc2[dn][2], acc2[dn][3]);
    }
}

// ---------------- launch ----------------
extern "C" void kernel_launch(void* const* d_in, const int* in_sizes, int n_in,
                              void* d_out, int out_size) {
    const float* x    = (const float*)d_in[0];
    const float* ln_g = (const float*)d_in[1];
    const float* ln_b = (const float*)d_in[2];
    const float* Wq   = (const float*)d_in[3];
    const float* bq   = (const float*)d_in[4];
    const float* Wk   = (const float*)d_in[5];
    const float* bk   = (const float*)d_in[6];
    const float* Wv   = (const float*)d_in[7];
    const float* bv   = (const float*)d_in[8];
    const float* Wo   = (const float*)d_in[9];
    const float* bo   = (const float*)d_in[10];
    float* out = (float*)d_out;

    __half *xn, *qkv, *wf, *wo, *attn, *vt;
    float *bf, *gl;
    cudaGetSymbolAddress((void**)&xn,   g_xn);
    cudaGetSymbolAddress((void**)&qkv,  g_qkv);
    cudaGetSymbolAddress((void**)&wf,   g_wf);
    cudaGetSymbolAddress((void**)&bf,   g_bf);
    cudaGetSymbolAddress((void**)&wo,   g_wo);
    cudaGetSymbolAddress((void**)&attn, g_attn);
    cudaGetSymbolAddress((void**)&vt,   g_vt);
    cudaGetSymbolAddress((void**)&gl,   g_gl);

    cudaFuncSetAttribute(gemm_f16<1>, cudaFuncAttributeMaxDynamicSharedMemorySize, GEMM_SMEM);
    cudaFuncSetAttribute(gemm_f16<0>, cudaFuncAttributeMaxDynamicSharedMemorySize, GEMM_SMEM);
    cudaFuncSetAttribute(stats_pass,  cudaFuncAttributeMaxDynamicSharedMemorySize, STATS_SMEM);
    cudaFuncSetAttribute(out_pass,    cudaFuncAttributeMaxDynamicSharedMemorySize, OUT_SMEM);

    fused_pre<<<NB_LN + NB_WQKV + NB_WO + NB_BIAS, 256>>>(
        x, ln_g, ln_b, Wq, Wk, Wv, Wo, bq, bk, bv, xn, wf, wo, bf);

    gemm_f16<1><<<dim3(QKVW / 128, ROWS / 128), 256, GEMM_SMEM>>>(
        xn, wf, bf, qkv, ROWS, QKVW, Dn, QSCALE, 1.0f, 2048);

    vtrans<<<dim3(Sn / 32, 512 / 32, Bn), 256>>>(qkv, vt);

    stats_pass<<<dim3(NTB128, NG), 256, STATS_SMEM>>>(qkv, gl);
    out_pass<<<dim3(NTB128, NG), 256, OUT_SMEM>>>(qkv, vt, gl, attn);

    gemm_f16<0><<<dim3(Dn / 128, ROWS / 128), 256, GEMM_SMEM>>>(
        attn, wo, bo, out, ROWS, Dn, HQn * HDn, 1.0f, 1.0f, 0);
}

// round 17
// speedup vs baseline: 2.1413x; 1.0216x over previous
#include <cuda_runtime.h>
#include <cuda_fp16.h>
#include <cuda_bf16.h>
#include <cstdint>
#include <math.h>

#define Bn 2
#define Sn 2048
#define Dn 2048
#define HQn 32
#define HKVn 8
#define HDn 64
#define ROWS (Bn * Sn)
#define NG   (Bn * HQn)
#define NTB64 (Sn / 64)
#define NTB128 (Sn / 128)
#define QKVW 3072
#define QSCALE 0.18033688011112042f   // 0.125 * log2(e)
#define ZOFF 20.0f                    // fixed exp2 offset for Z accumulation

// ---------------- scratch ----------------
__device__ __half g_xn[ROWS * Dn];
__device__ __half g_qkv[(size_t)ROWS * QKVW];
__device__ __half g_wf[(size_t)QKVW * Dn];         // transposed [n][k]
__device__ float  g_bf[QKVW];
__device__ __half g_wo[(size_t)Dn * Dn];           // transposed [n][k]
__device__ __half g_attn[ROWS * (HQn * HDn)];
__device__ __half g_vt[(size_t)Bn * 512 * Sn];     // V transposed [b][h*64+d][T]
__device__ float  g_gl[NG * Sn];                   // ZOFF + log2(Z)

// ---------------- helpers ----------------
__device__ __forceinline__ float fex2(float x) {
    float r; asm("ex2.approx.ftz.f32 %0, %1;" : "=f"(r) : "f"(x)); return r;
}
__device__ __forceinline__ float flg2(float x) {
    float r; asm("lg2.approx.ftz.f32 %0, %1;" : "=f"(r) : "f"(x)); return r;
}
__device__ __forceinline__ uint32_t pack2h(float x, float y) {
    __half2 h = __floats2half2_rn(x, y);
    return *(uint32_t*)&h;
}
__device__ __forceinline__ void mma16(float* c, uint32_t a0, uint32_t a1, uint32_t a2,
                                      uint32_t a3, uint32_t b0, uint32_t b1) {
    asm volatile(
        "mma.sync.aligned.m16n8k16.row.col.f32.f16.f16.f32 "
        "{%0,%1,%2,%3}, {%4,%5,%6,%7}, {%8,%9}, {%0,%1,%2,%3};"
        : "+f"(c[0]), "+f"(c[1]), "+f"(c[2]), "+f"(c[3])
        : "r"(a0), "r"(a1), "r"(a2), "r"(a3), "r"(b0), "r"(b1));
}
__device__ __forceinline__ void ldsm4(uint32_t* r, uint32_t addr) {
    asm volatile("ldmatrix.sync.aligned.m8n8.x4.shared.b16 {%0,%1,%2,%3}, [%4];"
        : "=r"(r[0]), "=r"(r[1]), "=r"(r[2]), "=r"(r[3]) : "r"(addr));
}
__device__ __forceinline__ uint32_t s2u(const void* p) {
    return (uint32_t)__cvta_generic_to_shared(p);
}
__device__ __forceinline__ void cpa16(void* dst_smem, const void* src) {
    uint32_t d = (uint32_t)__cvta_generic_to_shared(dst_smem);
    asm volatile("cp.async.cg.shared.global [%0], [%1], 16;" :: "r"(d), "l"(src));
}
#define CP_COMMIT() asm volatile("cp.async.commit_group;")
#define CP_WAIT(n)  asm volatile("cp.async.wait_group %0;" :: "n"(n))
#define NEGBIG (-1e30f)

// ---------------- fused pre: single-pass LN + weight transpose/convert + bias ----------------
#define NB_LN   ROWS
#define NB_WQKV ((Dn / 32) * (QKVW / 32))
#define NB_WO   ((Dn / 32) * (Dn / 32))
#define NB_BIAS 12
__global__ __launch_bounds__(256) void fused_pre(
    const float* __restrict__ x, const float* __restrict__ gamma,
    const float* __restrict__ beta,
    const float* __restrict__ Wq, const float* __restrict__ Wk,
    const float* __restrict__ Wv, const float* __restrict__ Wo,
    const float* __restrict__ bq, const float* __restrict__ bk,
    const float* __restrict__ bv,
    __half* __restrict__ xn, __half* __restrict__ Wf,
    __half* __restrict__ Wr, float* __restrict__ bf)
{
    __shared__ float red[256];
    __shared__ float red2[256];
    __shared__ __half tileh[32][33];
    const int blk = blockIdx.x;
    const int tid = threadIdx.x;

    if (blk < NB_LN) {
        const int row = blk;
        const float* xr = x + (size_t)row * Dn;
        __half* outr = xn + (size_t)row * Dn;
        const int base = tid * 8;

        const float4 v0 = *(const float4*)&xr[base];
        const float4 v1 = *(const float4*)&xr[base + 4];
        float s  = v0.x + v0.y + v0.z + v0.w + v1.x + v1.y + v1.z + v1.w;
        float s2 = v0.x * v0.x + v0.y * v0.y + v0.z * v0.z + v0.w * v0.w
                 + v1.x * v1.x + v1.y * v1.y + v1.z * v1.z + v1.w * v1.w;
        red[tid] = s; red2[tid] = s2; __syncthreads();
        for (int off = 128; off > 0; off >>= 1) {
            if (tid < off) { red[tid] += red[tid + off]; red2[tid] += red2[tid + off]; }
            __syncthreads();
        }
        const float mu = red[0] * (1.0f / Dn);
        const float var = red2[0] * (1.0f / Dn) - mu * mu;
        const float rstd = rsqrtf(var + 1e-5f);

        const float4 g0 = *(const float4*)&gamma[base];
        const float4 g1 = *(const float4*)&gamma[base + 4];
        const float4 b0 = *(const float4*)&beta[base];
        const float4 b1 = *(const float4*)&beta[base + 4];
        uint4 o;
        o.x = pack2h((v0.x - mu) * rstd * g0.x + b0.x, (v0.y - mu) * rstd * g0.y + b0.y);
        o.y = pack2h((v0.z - mu) * rstd * g0.z + b0.z, (v0.w - mu) * rstd * g0.w + b0.w);
        o.z = pack2h((v1.x - mu) * rstd * g1.x + b1.x, (v1.y - mu) * rstd * g1.y + b1.y);
        o.w = pack2h((v1.z - mu) * rstd * g1.z + b1.z, (v1.w - mu) * rstd * g1.w + b1.w);
        *(uint4*)&outr[base] = o;
    } else if (blk < NB_LN + NB_WQKV) {
        const int tidx = blk - NB_LN;
        const int tk = tidx & 63, tn = tidx >> 6;
        const int tx = tid & 31, ty = tid >> 5;
        #pragma unroll
        for (int i = 0; i < 32; i += 8) {
            const int k = tk * 32 + ty + i;
            const int n = tn * 32 + tx;
            float val;
            if (n < 2048)      val = Wq[(size_t)k * 2048 + n];
            else if (n < 2560) val = Wk[(size_t)k * 512 + n - 2048];
            else               val = Wv[(size_t)k * 512 + n - 2560];
            tileh[ty + i][tx] = __float2half(val);
        }
        __syncthreads();
        #pragma unroll
        for (int i = 0; i < 32; i += 8)
            Wf[(size_t)(tn * 32 + ty + i) * Dn + tk * 32 + tx] = tileh[tx][ty + i];
    } else if (blk < NB_LN + NB_WQKV + NB_WO) {
        const int tidx = blk - NB_LN - NB_WQKV;
        const int tk = tidx & 63, tn = tidx >> 6;
        const int tx = tid & 31, ty = tid >> 5;
        #pragma unroll
        for (int i = 0; i < 32; i += 8)
            tileh[ty + i][tx] = __float2half(Wo[(size_t)(tk * 32 + ty + i) * 2048 + tn * 32 + tx]);
        __syncthreads();
        #pragma unroll
        for (int i = 0; i < 32; i += 8)
            Wr[(size_t)(tn * 32 + ty + i) * Dn + tk * 32 + tx] = tileh[tx][ty + i];
    } else {
        const int col = (blk - NB_LN - NB_WQKV - NB_WO) * 256 + tid;
        if (col < QKVW)
            bf[col] = col < 2048 ? bq[col] : (col < 2560 ? bk[col - 2048] : bv[col - 2560]);
    }
}

// ---------------- fp16 GEMM with ldmatrix, 4-stage cp.async ----------------
#define GSTAGES 4
#define GEMM_SMEM (GSTAGES * 2 * 128 * 40 * 2)

template<int HALF_OUT>
__global__ __launch_bounds__(256, 2) void gemm_f16(
    const __half* __restrict__ A, const __half* __restrict__ Bt,
    const float* __restrict__ bias, void* __restrict__ Cv,
    int M, int N, int K, float scale0, float scale1, int ncut)
{
    extern __shared__ __half smh[];
    __half (*As)[128][40] = (__half(*)[128][40])smh;
    __half (*Bs)[128][40] = (__half(*)[128][40])(smh + GSTAGES * 128 * 40);

    const int tid = threadIdx.x;
    const int lane = tid & 31, wid = tid >> 5;
    const int warp_m = wid & 3, warp_n = wid >> 2;
    const int m0 = blockIdx.y * 128, n0 = blockIdx.x * 128;
    const int lr = lane >> 2, lc = lane & 3;

    const int aoff = (warp_m * 32 + (lane & 15)) * 80 + (lane >> 4) * 16;
    const int boff = (warp_n * 64 + (lane >> 4) * 8 + (lane & 7)) * 80 + ((lane >> 3) & 1) * 16;

    const int KT = K / 32;

    float acc[2][8][4];
    #pragma unroll
    for (int i = 0; i < 2; i++)
        #pragma unroll
        for (int j = 0; j < 8; j++)
            #pragma unroll
            for (int q = 0; q < 4; q++) acc[i][j][q] = 0.f;

    #pragma unroll
    for (int s = 0; s < GSTAGES - 1; s++) {
        const int k0 = s * 32;
        #pragma unroll
        for (int t = tid; t < 512; t += 256) {
            const int row = t >> 2, cg = (t & 3) * 8;
            cpa16(&As[s][row][cg], &A[(size_t)(m0 + row) * K + k0 + cg]);
            cpa16(&Bs[s][row][cg], &Bt[(size_t)(n0 + row) * K + k0 + cg]);
        }
        CP_COMMIT();
    }

    for (int kt = 0; kt < KT; kt++) {
        CP_WAIT(GSTAGES - 2);
        __syncthreads();

        const int nf = kt + GSTAGES - 1;
        if (nf < KT) {
            const int s = nf % GSTAGES;
            const int k0 = nf * 32;
            #pragma unroll
            for (int t = tid; t < 512; t += 256) {
                const int row = t >> 2, cg = (t & 3) * 8;
                cpa16(&As[s][row][cg], &A[(size_t)(m0 + row) * K + k0 + cg]);
                cpa16(&Bs[s][row][cg], &Bt[(size_t)(n0 + row) * K + k0 + cg]);
            }
        }
        CP_COMMIT();

        const int cur = kt % GSTAGES;
        const uint32_t sA = s2u(&As[cur][0][0]);
        const uint32_t sB = s2u(&Bs[cur][0][0]);
        #pragma unroll
        for (int ks = 0; ks < 2; ks++) {
            const int kbb = ks * 32;
            uint32_t af[2][4];
            ldsm4(af[0], sA + aoff + kbb);
            ldsm4(af[1], sA + aoff + 16 * 80 + kbb);
            #pragma unroll
            for (int p = 0; p < 4; p++) {
                uint32_t bq[4];
                ldsm4(bq, sB + boff + p * 16 * 80 + kbb);
                #pragma unroll
                for (int im = 0; im < 2; im++) {
                    mma16(acc[im][2 * p],     af[im][0], af[im][1], af[im][2], af[im][3], bq[0], bq[1]);
                    mma16(acc[im][2 * p + 1], af[im][0], af[im][1], af[im][2], af[im][3], bq[2], bq[3]);
                }
            }
        }
    }

    #pragma unroll
    for (int im = 0; im < 2; im++)
        #pragma unroll
        for (int jn = 0; jn < 8; jn++) {
            const int row = m0 + warp_m * 32 + im * 16 + lr;
            const int col = n0 + warp_n * 64 + jn * 8 + lc * 2;
            const float sc = (col < ncut) ? scale0 : scale1;
            const float bb0 = bias[col], bb1 = bias[col + 1];
            const float v00 = sc * (acc[im][jn][0] + bb0);
            const float v01 = sc * (acc[im][jn][1] + bb1);
            const float v10 = sc * (acc[im][jn][2] + bb0);
            const float v11 = sc * (acc[im][jn][3] + bb1);
            if (HALF_OUT) {
                __half* C = (__half*)Cv;
                *(uint32_t*)&C[(size_t)row * N + col] = pack2h(v00, v01);
                *(uint32_t*)&C[(size_t)(row + 8) * N + col] = pack2h(v10, v11);
            } else {
                float* C = (float*)Cv;
                *(float2*)&C[(size_t)row * N + col] = make_float2(v00, v01);
                *(float2*)&C[(size_t)(row + 8) * N + col] = make_float2(v10, v11);
            }
        }
}

// ---------------- V transpose ----------------
__global__ __launch_bounds__(256) void vtrans(
    const __half* __restrict__ QKV, __half* __restrict__ vT)
{
    __shared__ __half tile[32][33];
    const int b = blockIdx.z;
    const int hd0 = blockIdx.y * 32;
    const int t0 = blockIdx.x * 32;
    const int tx = threadIdx.x & 31, ty = threadIdx.x >> 5;

    #pragma unroll
    for (int i = 0; i < 32; i += 8)
        tile[ty + i][tx] = QKV[(size_t)(b * Sn + t0 + ty + i) * QKVW + 2560 + hd0 + tx];
    __syncthreads();
    #pragma unroll
    for (int i = 0; i < 32; i += 8)
        vT[(size_t)(b * 512 + hd0 + ty + i) * Sn + t0 + tx] = tile[tx][ty + i];
}

// ---------------- pass 1: fixed-offset column Z -> gl = ZOFF + log2(Z) ----------------
#define STATS_SMEM ((128 * 72 + 2 * 64 * 72) * 2)
__global__ __launch_bounds__(256, 3) void stats_pass(
    const __half* __restrict__ QKV, float* __restrict__ ggl)
{
    extern __shared__ __half smh[];
    __half (*Ks)[72] = (__half(*)[72])smh;
    __half (*Qs)[64][72] = (__half(*)[64][72])(smh + 128 * 72);

    const int g = blockIdx.y;
    const int b = g >> 5, hq = g & 31, h = hq >> 2;
    const int Tb = blockIdx.x;
    const int T0 = Tb * 128;

    const int tid = threadIdx.x;
    const int lane = tid & 31, w = tid >> 5;
    const int lr = lane >> 2, lc = lane & 3;

    const int aoff = (w * 16 + (lane & 15)) * 144 + (lane >> 4) * 16;
    const int boff = ((lane >> 4) * 8 + (lane & 7)) * 144 + ((lane >> 3) & 1) * 16;

    const __half* Kbase = QKV + 2048 + h * HDn;
    const __half* Qbase = QKV + hq * HDn;

    #pragma unroll
    for (int p = 0; p < 4; p++) {
        const int row = p * 32 + (tid >> 3);
        const int c8 = (tid & 7) * 8;
        *(float4*)&Ks[row][c8] =
            *(const float4*)&Kbase[(size_t)(b * Sn + T0 + row) * QKVW + c8];
    }
    const uint32_t sK = s2u(&Ks[0][0]);

    const int tb0 = 2 * Tb;
    #pragma unroll
    for (int t = tid; t < 512; t += 256) {
        const int row = t >> 3, c8 = (t & 7) * 8;
        cpa16(&Qs[0][row][c8], &Qbase[(size_t)(b * Sn + tb0 * 64 + row) * QKVW + c8]);
    }
    CP_COMMIT();

    const int Trow0 = T0 + w * 16 + lr;
    const int Trow1 = Trow0 + 8;

    float z0 = 0.f, z1 = 0.f;

    for (int tb = tb0; tb < NTB64; tb++) {
        const int cur = (tb - tb0) & 1;
        __syncthreads();
        if (tb + 1 < NTB64) {
            #pragma unroll
            for (int t = tid; t < 512; t += 256) {
                const int row = t >> 3, c8 = (t & 7) * 8;
                cpa16(&Qs[cur ^ 1][row][c8],
                      &Qbase[(size_t)(b * Sn + (tb + 1) * 64 + row) * QKVW + c8]);
            }
        }
        CP_COMMIT();
        CP_WAIT(1);
        __syncthreads();

        float acc[8][4];
        #pragma unroll
        for (int j = 0; j < 8; j++)
            #pragma unroll
            for (int q = 0; q < 4; q++) acc[j][q] = 0.f;

        const uint32_t sQ = s2u(&Qs[cur][0][0]);
        #pragma unroll
        for (int ks = 0; ks < 4; ks++) {
            const int kbb = ks * 32;
            uint32_t a[4];
            ldsm4(a, sK + aoff + kbb);
            #pragma unroll
            for (int p = 0; p < 4; p++) {
                uint32_t bq[4];
                ldsm4(bq, sQ + boff + p * 16 * 144 + kbb);
                mma16(acc[2 * p],     a[0], a[1], a[2], a[3], bq[0], bq[1]);
                mma16(acc[2 * p + 1], a[0], a[1], a[2], a[3], bq[2], bq[3]);
            }
        }

        // masking (first 2 tiles only)
        if (tb <= tb0 + 1) {
            const int tbase = tb * 64 + lc * 2;
            #pragma unroll
            for (int jn = 0; jn < 8; jn++) {
                const int tcol = tbase + jn * 8;
                if (tcol     < Trow0) acc[jn][0] = NEGBIG;
                if (tcol + 1 < Trow0) acc[jn][1] = NEGBIG;
                if (tcol     < Trow1) acc[jn][2] = NEGBIG;
                if (tcol + 1 < Trow1) acc[jn][3] = NEGBIG;
            }
        }

        // fixed-offset Z accumulation (no online max)
        #pragma unroll
        for (int jn = 0; jn < 8; jn++) {
            z0 += fex2(acc[jn][0] - ZOFF) + fex2(acc[jn][1] - ZOFF);
            z1 += fex2(acc[jn][2] - ZOFF) + fex2(acc[jn][3] - ZOFF);
        }
    }

    // quad-sum (lanes sharing a row)
    #pragma unroll
    for (int off = 1; off < 4; off <<= 1) {
        z0 += __shfl_xor_sync(0xffffffffu, z0, off);
        z1 += __shfl_xor_sync(0xffffffffu, z1, off);
    }
    if (lc == 0) {
        ggl[g * Sn + Trow0] = ZOFF + flg2(z0);
        ggl[g * Sn + Trow1] = ZOFF + flg2(z1);
    }
}

// ---------------- pass 2: register-P flash, f32 exp epilogue ----------------
#define OUT_SMEM ((128 * 72 + 2 * 64 * 72 + 2 * 64 * 72) * 2 + 2 * 64 * 4)
__global__ __launch_bounds__(256, 2) void out_pass(
    const __half* __restrict__ QKV, const __half* __restrict__ vT,
    const float* __restrict__ ggl, __half* __restrict__ O)
{
    extern __shared__ __half smh[];
    __half (*Qs)[72] = (__half(*)[72])smh;
    __half (*Ks)[64][72] = (__half(*)[64][72])(smh + 128 * 72);
    __half (*Vt)[64][72] = (__half(*)[64][72])(smh + 128 * 72 + 2 * 64 * 72);
    float* s_gl = (float*)(smh + 128 * 72 + 4 * 64 * 72);

    const int g = blockIdx.y;
    const int b = g >> 5, hq = g & 31, h = hq >> 2;
    const int tblk = (NTB128 - 1) - blockIdx.x;
    const int t0 = tblk * 128;

    const int tid = threadIdx.x;
    const int lane = tid & 31, w = tid >> 5;
    const int lr = lane >> 2, lc = lane & 3;

    const int aoff = (w * 16 + (lane & 15)) * 144 + (lane >> 4) * 16;
    const int boff = ((lane >> 4) * 8 + (lane & 7)) * 144 + ((lane >> 3) & 1) * 16;

    const __half* Qbase = QKV + hq * HDn;
    const __half* Kbase = QKV + 2048 + h * HDn;
    const __half* Vtb = vT + (size_t)(b * 512 + h * HDn) * Sn;

    #pragma unroll
    for (int p = 0; p < 4; p++) {
        const int t = p * 256 + tid;
        const int row = t >> 3, c8 = (t & 7) * 8;
        *(float4*)&Qs[row][c8] =
            *(const float4*)&Qbase[(size_t)(b * Sn + t0 + row) * QKVW + c8];
    }
    const uint32_t sQ = s2u(&Qs[0][0]);

    #pragma unroll
    for (int t = tid; t < 512; t += 256) {
        const int row = t >> 3, c8 = (t & 7) * 8;
        cpa16(&Ks[0][row][c8], &Kbase[(size_t)(b * Sn + row) * QKVW + c8]);
        cpa16(&Vt[0][row][c8], &Vtb[(size_t)row * Sn + c8]);
    }
    if (tid < 16) cpa16(&s_gl[tid * 4], &ggl[g * Sn + tid * 4]);
    CP_COMMIT();

    float acc2[8][4];
    #pragma unroll
    for (int j = 0; j < 8; j++)
        #pragma unroll
        for (int q = 0; q < 4; q++) acc2[j][q] = 0.f;

    const int trg0 = t0 + w * 16 + lr;
    const int trg1 = trg0 + 8;

    const int nT = 2 * tblk + 2;
    for (int Tb = 0; Tb < nT; Tb++) {
        const int T0 = Tb * 64;
        const int cur = Tb & 1;

        __syncthreads();
        if (Tb + 1 < nT) {
            const int Tn = (Tb + 1) * 64;
            const int nxt = cur ^ 1;
            #pragma unroll
            for (int t = tid; t < 512; t += 256) {
                const int row = t >> 3, c8 = (t & 7) * 8;
                cpa16(&Ks[nxt][row][c8], &Kbase[(size_t)(b * Sn + Tn + row) * QKVW + c8]);
                cpa16(&Vt[nxt][row][c8], &Vtb[(size_t)row * Sn + Tn + c8]);
            }
            if (tid < 16) cpa16(&s_gl[nxt * 64 + tid * 4], &ggl[g * Sn + Tn + tid * 4]);
        }
        CP_COMMIT();
        CP_WAIT(1);
        __syncthreads();

        // stage 1: S = Q . K
        float acc1[8][4];
        #pragma unroll
        for (int j = 0; j < 8; j++)
            #pragma unroll
            for (int q = 0; q < 4; q++) acc1[j][q] = 0.f;

        const uint32_t sK = s2u(&Ks[cur][0][0]);
        #pragma unroll
        for (int ks = 0; ks < 4; ks++) {
            const int kbb = ks * 32;
            uint32_t a[4];
            ldsm4(a, sQ + aoff + kbb);
            #pragma unroll
            for (int p = 0; p < 4; p++) {
                uint32_t bq[4];
                ldsm4(bq, sK + boff + p * 16 * 144 + kbb);
                mma16(acc1[2 * p],     a[0], a[1], a[2], a[3], bq[0], bq[1]);
                mma16(acc1[2 * p + 1], a[0], a[1], a[2], a[3], bq[2], bq[3]);
            }
        }

        // softmax apply: f32 exp, pack to fp16 fragments
        const float* smv = &s_gl[cur * 64];
        const bool diag = (Tb >= 2 * tblk);
        uint32_t aP[8][2];
        #pragma unroll
        for (int jn = 0; jn < 8; jn++) {
            const int Tcol = jn * 8 + 2 * lc;
            const int Tg = T0 + Tcol;
            const float2 gl = *(const float2*)&smv[Tcol];
            float p00 = fex2(acc1[jn][0] - gl.x);
            float p01 = fex2(acc1[jn][1] - gl.y);
            float p10 = fex2(acc1[jn][2] - gl.x);
            float p11 = fex2(acc1[jn][3] - gl.y);
            if (diag) {
                if (trg0 < Tg)     p00 = 0.f;
                if (trg0 < Tg + 1) p01 = 0.f;
                if (trg1 < Tg)     p10 = 0.f;
                if (trg1 < Tg + 1) p11 = 0.f;
            }
            aP[jn][0] = pack2h(p00, p01);
            aP[jn][1] = pack2h(p10, p11);
        }

        // stage 2: O += P @ V
        const uint32_t sV = s2u(&Vt[cur][0][0]);
        #pragma unroll
        for (int kt = 0; kt < 4; kt++) {
            const uint32_t a0 = aP[2 * kt][0];
            const uint32_t a1 = aP[2 * kt][1];
            const uint32_t a2 = aP[2 * kt + 1][0];
            const uint32_t a3 = aP[2 * kt + 1][1];
            const int kbb = kt * 32;
            #pragma unroll
            for (int p = 0; p < 4; p++) {
                uint32_t bv4[4];
                ldsm4(bv4, sV + boff + p * 16 * 144 + kbb);
                mma16(acc2[2 * p],     a0, a1, a2, a3, bv4[0], bv4[1]);
                mma16(acc2[2 * p + 1], a0, a1, a2, a3, bv4[2], bv4[3]);
            }
        }
    }

    #pragma unroll
    for (int dn = 0; dn < 8; dn++) {
        const int col = hq * HDn + dn * 8 + lc * 2;
        *(uint32_t*)&O[(size_t)(b * Sn + trg0) * (HQn * HDn) + col] =
            pack2h(acc2[dn][0], acc2[dn][1]);
        *(uint32_t*)&O[(size_t)(b * Sn + trg1) * (HQn * HDn) + col] =
            pack2h(acc2[dn][2], acc2[dn][3]);
    }
}

// ---------------- launch ----------------
extern "C" void kernel_launch(void* const* d_in, const int* in_sizes, int n_in,
                              void* d_out, int out_size) {
    const float* x    = (const float*)d_in[0];
    const float* ln_g = (const float*)d_in[1];
    const float* ln_b = (const float*)d_in[2];
    const float* Wq   = (const float*)d_in[3];
    const float* bq   = (const float*)d_in[4];
    const float* Wk   = (const float*)d_in[5];
    const float* bk   = (const float*)d_in[6];
    const float* Wv   = (const float*)d_in[7];
    const float* bv   = (const float*)d_in[8];
    const float* Wo   = (const float*)d_in[9];
    const float* bo   = (const float*)d_in[10];
    float* out = (float*)d_out;

    __half *xn, *qkv, *wf, *wo, *attn, *vt;
    float *bf, *gl;
    cudaGetSymbolAddress((void**)&xn,   g_xn);
    cudaGetSymbolAddress((void**)&qkv,  g_qkv);
    cudaGetSymbolAddress((void**)&wf,   g_wf);
    cudaGetSymbolAddress((void**)&bf,   g_bf);
    cudaGetSymbolAddress((void**)&wo,   g_wo);
    cudaGetSymbolAddress((void**)&attn, g_attn);
    cudaGetSymbolAddress((void**)&vt,   g_vt);
    cudaGetSymbolAddress((void**)&gl,   g_gl);

    cudaFuncSetAttribute(gemm_f16<1>, cudaFuncAttributeMaxDynamicSharedMemorySize, GEMM_SMEM);
    cudaFuncSetAttribute(gemm_f16<0>, cudaFuncAttributeMaxDynamicSharedMemorySize, GEMM_SMEM);
    cudaFuncSetAttribute(stats_pass,  cudaFuncAttributeMaxDynamicSharedMemorySize, STATS_SMEM);
    cudaFuncSetAttribute(out_pass,    cudaFuncAttributeMaxDynamicSharedMemorySize, OUT_SMEM);

    fused_pre<<<NB_LN + NB_WQKV + NB_WO + NB_BIAS, 256>>>(
        x, ln_g, ln_b, Wq, Wk, Wv, Wo, bq, bk, bv, xn, wf, wo, bf);

    gemm_f16<1><<<dim3(QKVW / 128, ROWS / 128), 256, GEMM_SMEM>>>(
        xn, wf, bf, qkv, ROWS, QKVW, Dn, QSCALE, 1.0f, 2048);

    vtrans<<<dim3(Sn / 32, 512 / 32, Bn), 256>>>(qkv, vt);

    stats_pass<<<dim3(NTB128, NG), 256, STATS_SMEM>>>(qkv, gl);
    out_pass<<<dim3(NTB128, NG), 256, OUT_SMEM>>>(qkv, vt, gl, attn);

    gemm_f16<0><<<dim3(Dn / 128, ROWS / 128), 256, GEMM_SMEM>>>(
        attn, wo, bo, out, ROWS, Dn, HQn * HDn, 1.0f, 1.0f, 0);
}